// round 4
// baseline (speedup 1.0000x reference)
#include <cuda_runtime.h>
#include <cuda_bf16.h>
#include <cstdint>

#define Ss  2048
#define Dd  1024
#define Hh  16
#define BH  64
#define BSz 8192

// Scratch (__device__ globals; no allocation)
__device__ __nv_bfloat16 g_Qhi[(size_t)BH * Ss * 64];
__device__ __nv_bfloat16 g_Qlo[(size_t)BH * Ss * 64];
__device__ __nv_bfloat16 g_Khi[(size_t)BH * Ss * 64];
__device__ __nv_bfloat16 g_Klo[(size_t)BH * Ss * 64];
__device__ __nv_bfloat16 g_Vhi[(size_t)BH * Ss * 64];
__device__ __nv_bfloat16 g_Vlo[(size_t)BH * Ss * 64];
__device__ float g_ctx[(size_t)BSz * Dd];
__device__ float g_rowsum[(size_t)BH * Ss];

// ---------------------------------------------------------------------------
__device__ __forceinline__ void cp16(void* dst, const void* src) {
    uint32_t d;
    asm volatile("{ .reg .u64 t; cvta.to.shared.u64 t, %1; cvt.u32.u64 %0, t; }"
                 : "=r"(d) : "l"(dst));
    asm volatile("cp.async.cg.shared.global [%0], [%1], 16;" :: "r"(d), "l"(src));
}
#define CP_COMMIT() asm volatile("cp.async.commit_group;")
#define CP_WAIT(n)  asm volatile("cp.async.wait_group %0;" :: "n"(n))

__device__ __forceinline__ uint32_t pack_bf2(__nv_bfloat16 a, __nv_bfloat16 b) {
    return (uint32_t)__bfloat16_as_ushort(a) | ((uint32_t)__bfloat16_as_ushort(b) << 16);
}
__device__ __forceinline__ void split1(float x, __nv_bfloat16& h, __nv_bfloat16& l) {
    h = __float2bfloat16(x);
    l = __float2bfloat16(x - __bfloat162float(h));
}
__device__ __forceinline__ void mma_bf16(float c[4], const uint32_t a[4], const uint32_t b[2]) {
    asm volatile(
        "mma.sync.aligned.m16n8k16.row.col.f32.bf16.bf16.f32 "
        "{%0,%1,%2,%3}, {%4,%5,%6,%7}, {%8,%9}, {%0,%1,%2,%3};"
        : "+f"(c[0]), "+f"(c[1]), "+f"(c[2]), "+f"(c[3])
        : "r"(a[0]), "r"(a[1]), "r"(a[2]), "r"(a[3]), "r"(b[0]), "r"(b[1]));
}

__global__ void zero_k(float* p, int n) {
    int i = blockIdx.x * 256 + threadIdx.x;
    if (i < n) p[i] = 0.f;
}

// ---------------------------------------------------------------------------
// proj_k: Y = X[8192,1024] @ W[1024,1024] + bias.  z selects matrix set.
// DENSE=0: write bf16 hi/lo pairs in head-split layout. DENSE=1: fp32 [M,N].
// 512 thr, CTA 128x128, warp 32x32 (mt2 x nt4), BK=16, double-buffered smem.
// ---------------------------------------------------------------------------
template <int DENSE>
__global__ void __launch_bounds__(512, 1)
proj_k(const float* __restrict__ X0, const float* __restrict__ X1,
       const float* __restrict__ X2,
       const float* __restrict__ W0, const float* __restrict__ W1,
       const float* __restrict__ W2,
       const float* __restrict__ B0, const float* __restrict__ B1,
       const float* __restrict__ B2,
       __nv_bfloat16* __restrict__ H0, __nv_bfloat16* __restrict__ L0,
       __nv_bfloat16* __restrict__ H1, __nv_bfloat16* __restrict__ L1,
       __nv_bfloat16* __restrict__ H2, __nv_bfloat16* __restrict__ L2,
       float* __restrict__ OUT)
{
    const int z = blockIdx.z;
    const float* X  = z == 0 ? X0 : z == 1 ? X1 : X2;
    const float* W  = z == 0 ? W0 : z == 1 ? W1 : W2;
    const float* Bi = z == 0 ? B0 : z == 1 ? B1 : B2;
    __nv_bfloat16* Hd = z == 0 ? H0 : z == 1 ? H1 : H2;
    __nv_bfloat16* Ld = z == 0 ? L0 : z == 1 ? L1 : L2;

    __shared__ __nv_bfloat16 As[2][2][128][24];
    __shared__ __nv_bfloat16 Bs[2][2][16][136];

    const int tid = threadIdx.x, lane = tid & 31, warp = tid >> 5;
    const int g = lane >> 2, t = lane & 3;
    const int wm = warp >> 2, wn = warp & 3;
    const int bm = blockIdx.y * 128, bn = blockIdx.x * 128;

    const int ar = tid >> 2, ac = tid & 3;
    const int br = tid >> 5, bc = (tid & 31) * 4;

    float acc[2][4][4] = {};

    float4 ax = *(const float4*)(X + (size_t)(bm + ar) * 1024 + ac * 4);
    float4 bx = *(const float4*)(W + (size_t)br * 1024 + bn + bc);

    for (int it = 0; it < 64; ++it) {
        const int s = it & 1;
        {
            __nv_bfloat16 h0, h1, h2, h3, l0, l1, l2, l3;
            split1(ax.x, h0, l0); split1(ax.y, h1, l1);
            split1(ax.z, h2, l2); split1(ax.w, h3, l3);
            *(uint2*)&As[s][0][ar][ac * 4] = make_uint2(pack_bf2(h0, h1), pack_bf2(h2, h3));
            *(uint2*)&As[s][1][ar][ac * 4] = make_uint2(pack_bf2(l0, l1), pack_bf2(l2, l3));
            split1(bx.x, h0, l0); split1(bx.y, h1, l1);
            split1(bx.z, h2, l2); split1(bx.w, h3, l3);
            *(uint2*)&Bs[s][0][br][bc] = make_uint2(pack_bf2(h0, h1), pack_bf2(h2, h3));
            *(uint2*)&Bs[s][1][br][bc] = make_uint2(pack_bf2(l0, l1), pack_bf2(l2, l3));
        }
        if (it + 1 < 64) {
            const int k0 = (it + 1) * 16;
            ax = *(const float4*)(X + (size_t)(bm + ar) * 1024 + k0 + ac * 4);
            bx = *(const float4*)(W + (size_t)(k0 + br) * 1024 + bn + bc);
        }
        __syncthreads();

        const __nv_bfloat16* Ah = &As[s][0][0][0];
        const __nv_bfloat16* Al = &As[s][1][0][0];
        uint32_t af[2][2][4];
#pragma unroll
        for (int mt = 0; mt < 2; mt++) {
            const int r = wm * 32 + mt * 16;
#pragma unroll
            for (int hl = 0; hl < 2; hl++) {
                const __nv_bfloat16* P = hl ? Al : Ah;
                af[mt][hl][0] = *(const uint32_t*)(P + (r + g) * 24 + 2 * t);
                af[mt][hl][1] = *(const uint32_t*)(P + (r + g + 8) * 24 + 2 * t);
                af[mt][hl][2] = *(const uint32_t*)(P + (r + g) * 24 + 2 * t + 8);
                af[mt][hl][3] = *(const uint32_t*)(P + (r + g + 8) * 24 + 2 * t + 8);
            }
        }
        const unsigned short* Bh = (const unsigned short*)&Bs[s][0][0][0];
        const unsigned short* Bl = (const unsigned short*)&Bs[s][1][0][0];
        uint32_t bfr[4][2][2];
#pragma unroll
        for (int nt = 0; nt < 4; nt++) {
            const int n = wn * 32 + nt * 8 + g;
#pragma unroll
            for (int hl = 0; hl < 2; hl++) {
                const unsigned short* P = hl ? Bl : Bh;
                bfr[nt][hl][0] = (uint32_t)P[(2 * t) * 136 + n] |
                                 ((uint32_t)P[(2 * t + 1) * 136 + n] << 16);
                bfr[nt][hl][1] = (uint32_t)P[(2 * t + 8) * 136 + n] |
                                 ((uint32_t)P[(2 * t + 9) * 136 + n] << 16);
            }
        }
#pragma unroll
        for (int mt = 0; mt < 2; mt++)
#pragma unroll
            for (int nt = 0; nt < 4; nt++) {
                mma_bf16(acc[mt][nt], af[mt][0], bfr[nt][0]);
                mma_bf16(acc[mt][nt], af[mt][0], bfr[nt][1]);
                mma_bf16(acc[mt][nt], af[mt][1], bfr[nt][0]);
            }
    }

#pragma unroll
    for (int mt = 0; mt < 2; mt++) {
        const int row0 = bm + wm * 32 + mt * 16 + g;
#pragma unroll
        for (int nt = 0; nt < 4; nt++) {
            const int col = bn + wn * 32 + nt * 8 + 2 * t;
            const float b0 = Bi[col], b1 = Bi[col + 1];
            const float v00 = acc[mt][nt][0] + b0, v01 = acc[mt][nt][1] + b1;
            const float v10 = acc[mt][nt][2] + b0, v11 = acc[mt][nt][3] + b1;
            if (DENSE) {
                *(float2*)(OUT + (size_t)row0 * 1024 + col)       = make_float2(v00, v01);
                *(float2*)(OUT + (size_t)(row0 + 8) * 1024 + col) = make_float2(v10, v11);
            } else {
                const int hh = col >> 6, dc = col & 63;
                const int b_ = row0 >> 11;
                const size_t o0 = (((size_t)b_ * 16 + hh) * 2048 + (row0 & 2047)) * 64 + dc;
                const size_t o1 = (((size_t)b_ * 16 + hh) * 2048 + ((row0 + 8) & 2047)) * 64 + dc;
                __nv_bfloat16 h0, l0, h1, l1;
                split1(v00, h0, l0); split1(v01, h1, l1);
                *(uint32_t*)&Hd[o0] = pack_bf2(h0, h1);
                *(uint32_t*)&Ld[o0] = pack_bf2(l0, l1);
                split1(v10, h0, l0); split1(v11, h1, l1);
                *(uint32_t*)&Hd[o1] = pack_bf2(h0, h1);
                *(uint32_t*)&Ld[o1] = pack_bf2(l0, l1);
            }
        }
    }
}

// ---------------------------------------------------------------------------
// logits_k: e = exp(0.125 * Q K^T + mask*-1e9); rowsum += partials.
// 512 thr, CTA 128x128 per bh, full K=64 staged once via cp.async (bf16 hi/lo).
// ---------------------------------------------------------------------------
__global__ void __launch_bounds__(512, 1)
logits_k(const __nv_bfloat16* __restrict__ Qhi, const __nv_bfloat16* __restrict__ Qlo,
         const __nv_bfloat16* __restrict__ Khi, const __nv_bfloat16* __restrict__ Klo,
         const float* __restrict__ mask, float* __restrict__ attn,
         float* __restrict__ rowsum)
{
    extern __shared__ __nv_bfloat16 dyn[];
    __shared__ float red[128];

    const int bh = blockIdx.z, b = bh >> 4;
    const int bm = blockIdx.y * 128, bn = blockIdx.x * 128;
    const int tid = threadIdx.x, lane = tid & 31, warp = tid >> 5;
    const int g = lane >> 2, t = lane & 3;
    const int wm = warp >> 2, wn = warp & 3;

    if (tid < 128) red[tid] = 0.f;

#pragma unroll
    for (int j = 0; j < 8; j++) {
        const int id = j * 512 + tid;
        const int p = id >> 10, r = (id >> 3) & 127, ch = id & 7;
        const __nv_bfloat16* src =
            p == 0 ? Qhi + ((size_t)bh * 2048 + bm + r) * 64 + ch * 8 :
            p == 1 ? Qlo + ((size_t)bh * 2048 + bm + r) * 64 + ch * 8 :
            p == 2 ? Khi + ((size_t)bh * 2048 + bn + r) * 64 + ch * 8 :
                     Klo + ((size_t)bh * 2048 + bn + r) * 64 + ch * 8;
        cp16(dyn + p * 9216 + r * 72 + ch * 8, src);
    }
    CP_COMMIT(); CP_WAIT(0);
    __syncthreads();

    const __nv_bfloat16* Qh_ = dyn;
    const __nv_bfloat16* Ql_ = dyn + 9216;
    const __nv_bfloat16* Kh_ = dyn + 18432;
    const __nv_bfloat16* Kl_ = dyn + 27648;

    float acc[2][4][4] = {};
#pragma unroll
    for (int kc = 0; kc < 64; kc += 16) {
        uint32_t af[2][2][4];
#pragma unroll
        for (int mt = 0; mt < 2; mt++) {
            const int r = wm * 32 + mt * 16;
#pragma unroll
            for (int hl = 0; hl < 2; hl++) {
                const __nv_bfloat16* P = hl ? Ql_ : Qh_;
                af[mt][hl][0] = *(const uint32_t*)(P + (r + g) * 72 + kc + 2 * t);
                af[mt][hl][1] = *(const uint32_t*)(P + (r + g + 8) * 72 + kc + 2 * t);
                af[mt][hl][2] = *(const uint32_t*)(P + (r + g) * 72 + kc + 2 * t + 8);
                af[mt][hl][3] = *(const uint32_t*)(P + (r + g + 8) * 72 + kc + 2 * t + 8);
            }
        }
        uint32_t bfr[4][2][2];
#pragma unroll
        for (int nt = 0; nt < 4; nt++) {
            const int n = wn * 32 + nt * 8 + g;
#pragma unroll
            for (int hl = 0; hl < 2; hl++) {
                const __nv_bfloat16* P = hl ? Kl_ : Kh_;
                bfr[nt][hl][0] = *(const uint32_t*)(P + n * 72 + kc + 2 * t);
                bfr[nt][hl][1] = *(const uint32_t*)(P + n * 72 + kc + 2 * t + 8);
            }
        }
#pragma unroll
        for (int mt = 0; mt < 2; mt++)
#pragma unroll
            for (int nt = 0; nt < 4; nt++) {
                mma_bf16(acc[mt][nt], af[mt][0], bfr[nt][0]);
                mma_bf16(acc[mt][nt], af[mt][0], bfr[nt][1]);
                mma_bf16(acc[mt][nt], af[mt][1], bfr[nt][0]);
            }
    }

    float rs[2][2] = {};
#pragma unroll
    for (int mt = 0; mt < 2; mt++) {
        const int rl0 = wm * 32 + mt * 16 + g;
#pragma unroll
        for (int nt = 0; nt < 4; nt++) {
            const int cl = wn * 32 + nt * 8 + 2 * t;
            const int gc = bn + cl;
            const float mk0 = mask[(size_t)b * 2048 + gc] * -1e9f;
            const float mk1 = mask[(size_t)b * 2048 + gc + 1] * -1e9f;
            const float e00 = __expf(acc[mt][nt][0] * 0.125f + mk0);
            const float e01 = __expf(acc[mt][nt][1] * 0.125f + mk1);
            const float e10 = __expf(acc[mt][nt][2] * 0.125f + mk0);
            const float e11 = __expf(acc[mt][nt][3] * 0.125f + mk1);
            *(float2*)(attn + ((size_t)bh * 2048 + bm + rl0) * 2048 + gc)     = make_float2(e00, e01);
            *(float2*)(attn + ((size_t)bh * 2048 + bm + rl0 + 8) * 2048 + gc) = make_float2(e10, e11);
            rs[mt][0] += e00 + e01;
            rs[mt][1] += e10 + e11;
        }
    }
#pragma unroll
    for (int mt = 0; mt < 2; mt++)
#pragma unroll
        for (int hf = 0; hf < 2; hf++) {
            float v = rs[mt][hf];
            v += __shfl_xor_sync(0xffffffffu, v, 1);
            v += __shfl_xor_sync(0xffffffffu, v, 2);
            if (t == 0) atomicAdd(&red[wm * 32 + mt * 16 + hf * 8 + g], v);
        }
    __syncthreads();
    if (tid < 128) atomicAdd(&rowsum[(size_t)bh * 2048 + bm + tid], red[tid]);
}

// ---------------------------------------------------------------------------
// ctx_k: normalize attn in-place (fp32) + ctx = P @ V (split-bf16 MMA).
// 256 thr, CTA 128x64 per bh, BK=16 double-buffered.
// ---------------------------------------------------------------------------
__global__ void __launch_bounds__(256, 2)
ctx_k(float* __restrict__ attn,
      const __nv_bfloat16* __restrict__ Vhi, const __nv_bfloat16* __restrict__ Vlo,
      const float* __restrict__ rowsum, float* __restrict__ ctx)
{
    __shared__ __nv_bfloat16 As[2][2][128][24];
    __shared__ __nv_bfloat16 Vs[2][2][16][72];

    const int bh = blockIdx.z, b = bh >> 4, h = bh & 15;
    float* A = attn + (size_t)bh * 2048 * 2048;
    const int bm = blockIdx.x * 128;
    const int tid = threadIdx.x, lane = tid & 31, warp = tid >> 5;
    const int g = lane >> 2, t = lane & 3;
    const int wm = warp >> 1, wn = warp & 1;

    const int lr = tid >> 2, lc = tid & 3;
    const float inv0 = 1.f / rowsum[(size_t)bh * 2048 + bm + lr];
    const float inv1 = 1.f / rowsum[(size_t)bh * 2048 + bm + lr + 64];

    const int vp = tid >> 7, vid = tid & 127, vkr = vid >> 3, vch = vid & 7;
    const __nv_bfloat16* Vsrc = vp ? Vlo : Vhi;

    float4 a0 = *(const float4*)(A + (size_t)(bm + lr) * 2048 + lc * 4);
    float4 a1 = *(const float4*)(A + (size_t)(bm + lr + 64) * 2048 + lc * 4);
    cp16(&Vs[0][vp][vkr][vch * 8], Vsrc + ((size_t)bh * 2048 + vkr) * 64 + vch * 8);
    CP_COMMIT();

    float acc[2][4][4] = {};

    for (int it = 0; it < 128; ++it) {
        const int s = it & 1;
        const float4 p0 = make_float4(a0.x * inv0, a0.y * inv0, a0.z * inv0, a0.w * inv0);
        const float4 p1 = make_float4(a1.x * inv1, a1.y * inv1, a1.z * inv1, a1.w * inv1);
        *(float4*)(A + (size_t)(bm + lr) * 2048 + it * 16 + lc * 4)      = p0;
        *(float4*)(A + (size_t)(bm + lr + 64) * 2048 + it * 16 + lc * 4) = p1;
        {
            __nv_bfloat16 h0, h1, h2, h3, l0, l1, l2, l3;
            split1(p0.x, h0, l0); split1(p0.y, h1, l1);
            split1(p0.z, h2, l2); split1(p0.w, h3, l3);
            *(uint2*)&As[s][0][lr][lc * 4] = make_uint2(pack_bf2(h0, h1), pack_bf2(h2, h3));
            *(uint2*)&As[s][1][lr][lc * 4] = make_uint2(pack_bf2(l0, l1), pack_bf2(l2, l3));
            split1(p1.x, h0, l0); split1(p1.y, h1, l1);
            split1(p1.z, h2, l2); split1(p1.w, h3, l3);
            *(uint2*)&As[s][0][lr + 64][lc * 4] = make_uint2(pack_bf2(h0, h1), pack_bf2(h2, h3));
            *(uint2*)&As[s][1][lr + 64][lc * 4] = make_uint2(pack_bf2(l0, l1), pack_bf2(l2, l3));
        }
        if (it + 1 < 128) {
            const int k0 = (it + 1) * 16;
            a0 = *(const float4*)(A + (size_t)(bm + lr) * 2048 + k0 + lc * 4);
            a1 = *(const float4*)(A + (size_t)(bm + lr + 64) * 2048 + k0 + lc * 4);
        }
        CP_WAIT(0);
        __syncthreads();
        if (it + 1 < 128) {
            const int k0 = (it + 1) * 16;
            cp16(&Vs[s ^ 1][vp][vkr][vch * 8],
                 Vsrc + ((size_t)bh * 2048 + k0 + vkr) * 64 + vch * 8);
            CP_COMMIT();
        }

        const __nv_bfloat16* Ah = &As[s][0][0][0];
        const __nv_bfloat16* Al = &As[s][1][0][0];
        uint32_t af[2][2][4];
#pragma unroll
        for (int mt = 0; mt < 2; mt++) {
            const int r = wm * 32 + mt * 16;
#pragma unroll
            for (int hl = 0; hl < 2; hl++) {
                const __nv_bfloat16* P = hl ? Al : Ah;
                af[mt][hl][0] = *(const uint32_t*)(P + (r + g) * 24 + 2 * t);
                af[mt][hl][1] = *(const uint32_t*)(P + (r + g + 8) * 24 + 2 * t);
                af[mt][hl][2] = *(const uint32_t*)(P + (r + g) * 24 + 2 * t + 8);
                af[mt][hl][3] = *(const uint32_t*)(P + (r + g + 8) * 24 + 2 * t + 8);
            }
        }
        const unsigned short* Bh_ = (const unsigned short*)&Vs[s][0][0][0];
        const unsigned short* Bl_ = (const unsigned short*)&Vs[s][1][0][0];
        uint32_t bfr[4][2][2];
#pragma unroll
        for (int nt = 0; nt < 4; nt++) {
            const int n = wn * 32 + nt * 8 + g;
#pragma unroll
            for (int hl = 0; hl < 2; hl++) {
                const unsigned short* P = hl ? Bl_ : Bh_;
                bfr[nt][hl][0] = (uint32_t)P[(2 * t) * 72 + n] |
                                 ((uint32_t)P[(2 * t + 1) * 72 + n] << 16);
                bfr[nt][hl][1] = (uint32_t)P[(2 * t + 8) * 72 + n] |
                                 ((uint32_t)P[(2 * t + 9) * 72 + n] << 16);
            }
        }
#pragma unroll
        for (int mt = 0; mt < 2; mt++)
#pragma unroll
            for (int nt = 0; nt < 4; nt++) {
                mma_bf16(acc[mt][nt], af[mt][0], bfr[nt][0]);
                mma_bf16(acc[mt][nt], af[mt][0], bfr[nt][1]);
                mma_bf16(acc[mt][nt], af[mt][1], bfr[nt][0]);
            }
    }

#pragma unroll
    for (int mt = 0; mt < 2; mt++) {
        const int row0 = bm + wm * 32 + mt * 16 + g;
#pragma unroll
        for (int nt = 0; nt < 4; nt++) {
            const int col = wn * 32 + nt * 8 + 2 * t;
            *(float2*)(ctx + ((size_t)b * 2048 + row0) * 1024 + h * 64 + col) =
                make_float2(acc[mt][nt][0], acc[mt][nt][1]);
            *(float2*)(ctx + ((size_t)b * 2048 + row0 + 8) * 1024 + h * 64 + col) =
                make_float2(acc[mt][nt][2], acc[mt][nt][3]);
        }
    }
}

// ---------------------------------------------------------------------------
extern "C" void kernel_launch(void* const* d_in, const int* in_sizes, int n_in,
                              void* d_out, int out_size)
{
    const float* q    = (const float*)d_in[0];
    const float* k    = (const float*)d_in[1];
    const float* v    = (const float*)d_in[2];
    const float* mask = (const float*)d_in[3];
    const float* Wq   = (const float*)d_in[4];
    const float* bq   = (const float*)d_in[5];
    const float* Wk   = (const float*)d_in[6];
    const float* bk   = (const float*)d_in[7];
    const float* Wv   = (const float*)d_in[8];
    const float* bv   = (const float*)d_in[9];
    const float* Wo   = (const float*)d_in[10];
    const float* bo   = (const float*)d_in[11];

    float* out  = (float*)d_out;
    float* attn = out + (size_t)BSz * Dd;

    __nv_bfloat16 *Qhi, *Qlo, *Khi, *Klo, *Vhi, *Vlo;
    float *ctxp, *rowsum;
    cudaGetSymbolAddress((void**)&Qhi, g_Qhi);
    cudaGetSymbolAddress((void**)&Qlo, g_Qlo);
    cudaGetSymbolAddress((void**)&Khi, g_Khi);
    cudaGetSymbolAddress((void**)&Klo, g_Klo);
    cudaGetSymbolAddress((void**)&Vhi, g_Vhi);
    cudaGetSymbolAddress((void**)&Vlo, g_Vlo);
    cudaGetSymbolAddress((void**)&ctxp, g_ctx);
    cudaGetSymbolAddress((void**)&rowsum, g_rowsum);

    cudaFuncSetAttribute(logits_k, cudaFuncAttributeMaxDynamicSharedMemorySize, 73728);

    zero_k<<<512, 256>>>(rowsum, BH * Ss);

    proj_k<0><<<dim3(8, 64, 3), 512>>>(q, k, v, Wq, Wk, Wv, bq, bk, bv,
                                       Qhi, Qlo, Khi, Klo, Vhi, Vlo, nullptr);

    logits_k<<<dim3(16, 16, 64), 512, 73728>>>(Qhi, Qlo, Khi, Klo, mask, attn, rowsum);

    ctx_k<<<dim3(16, 1, 64), 256>>>(attn, Vhi, Vlo, rowsum, ctxp);

    proj_k<1><<<dim3(8, 64, 1), 512>>>(ctxp, ctxp, ctxp, Wo, Wo, Wo, bo, bo, bo,
                                       nullptr, nullptr, nullptr, nullptr,
                                       nullptr, nullptr, out);
}

// round 5
// speedup vs baseline: 1.0023x; 1.0023x over previous
#include <cuda_runtime.h>
#include <cuda_bf16.h>
#include <cuda_fp16.h>
#include <cstdint>

#define Ss  2048
#define Dd  1024
#define Hh  16
#define BH  64
#define BSz 8192

// Scratch (__device__ globals; no allocation)
__device__ __nv_bfloat16 g_Qhi[(size_t)BH * Ss * 64];
__device__ __nv_bfloat16 g_Qlo[(size_t)BH * Ss * 64];
__device__ __nv_bfloat16 g_Khi[(size_t)BH * Ss * 64];
__device__ __nv_bfloat16 g_Klo[(size_t)BH * Ss * 64];
__device__ __nv_bfloat16 g_Vhi[(size_t)BH * Ss * 64];
__device__ __nv_bfloat16 g_Vlo[(size_t)BH * Ss * 64];
__device__ float g_ctx[(size_t)BSz * Dd];
__device__ float g_rowsum[(size_t)BH * Ss];
__device__ __half g_e[(size_t)BH * Ss * Ss];   // unnormalized exp(logits), fp16

// ---------------------------------------------------------------------------
__device__ __forceinline__ void cp16(void* dst, const void* src) {
    uint32_t d;
    asm volatile("{ .reg .u64 t; cvta.to.shared.u64 t, %1; cvt.u32.u64 %0, t; }"
                 : "=r"(d) : "l"(dst));
    asm volatile("cp.async.cg.shared.global [%0], [%1], 16;" :: "r"(d), "l"(src));
}
#define CP_COMMIT() asm volatile("cp.async.commit_group;")
#define CP_WAIT(n)  asm volatile("cp.async.wait_group %0;" :: "n"(n))

__device__ __forceinline__ uint32_t pack_bf2(__nv_bfloat16 a, __nv_bfloat16 b) {
    return (uint32_t)__bfloat16_as_ushort(a) | ((uint32_t)__bfloat16_as_ushort(b) << 16);
}
__device__ __forceinline__ void split1(float x, __nv_bfloat16& h, __nv_bfloat16& l) {
    h = __float2bfloat16(x);
    l = __float2bfloat16(x - __bfloat162float(h));
}
__device__ __forceinline__ void mma_bf16(float c[4], const uint32_t a[4], const uint32_t b[2]) {
    asm volatile(
        "mma.sync.aligned.m16n8k16.row.col.f32.bf16.bf16.f32 "
        "{%0,%1,%2,%3}, {%4,%5,%6,%7}, {%8,%9}, {%0,%1,%2,%3};"
        : "+f"(c[0]), "+f"(c[1]), "+f"(c[2]), "+f"(c[3])
        : "r"(a[0]), "r"(a[1]), "r"(a[2]), "r"(a[3]), "r"(b[0]), "r"(b[1]));
}

__global__ void zero_k(float* p, int n) {
    int i = blockIdx.x * 256 + threadIdx.x;
    if (i < n) p[i] = 0.f;
}

// ---------------------------------------------------------------------------
// proj_k: unchanged from round 3 (known-good).
// ---------------------------------------------------------------------------
template <int DENSE>
__global__ void __launch_bounds__(512, 1)
proj_k(const float* __restrict__ X0, const float* __restrict__ X1,
       const float* __restrict__ X2,
       const float* __restrict__ W0, const float* __restrict__ W1,
       const float* __restrict__ W2,
       const float* __restrict__ B0, const float* __restrict__ B1,
       const float* __restrict__ B2,
       __nv_bfloat16* __restrict__ H0, __nv_bfloat16* __restrict__ L0,
       __nv_bfloat16* __restrict__ H1, __nv_bfloat16* __restrict__ L1,
       __nv_bfloat16* __restrict__ H2, __nv_bfloat16* __restrict__ L2,
       float* __restrict__ OUT)
{
    const int z = blockIdx.z;
    const float* X  = z == 0 ? X0 : z == 1 ? X1 : X2;
    const float* W  = z == 0 ? W0 : z == 1 ? W1 : W2;
    const float* Bi = z == 0 ? B0 : z == 1 ? B1 : B2;
    __nv_bfloat16* Hd = z == 0 ? H0 : z == 1 ? H1 : H2;
    __nv_bfloat16* Ld = z == 0 ? L0 : z == 1 ? L1 : L2;

    __shared__ __align__(16) __nv_bfloat16 As[2][2][128][24];
    __shared__ __align__(16) __nv_bfloat16 Bs[2][2][16][136];

    const int tid = threadIdx.x, lane = tid & 31, warp = tid >> 5;
    const int g = lane >> 2, t = lane & 3;
    const int wm = warp >> 2, wn = warp & 3;
    const int bm = blockIdx.y * 128, bn = blockIdx.x * 128;

    const int ar = tid >> 2, ac = tid & 3;
    const int br = tid >> 5, bc = (tid & 31) * 4;

    float acc[2][4][4] = {};

    float4 ax = *(const float4*)(X + (size_t)(bm + ar) * 1024 + ac * 4);
    float4 bx = *(const float4*)(W + (size_t)br * 1024 + bn + bc);

    for (int it = 0; it < 64; ++it) {
        const int s = it & 1;
        {
            __nv_bfloat16 h0, h1, h2, h3, l0, l1, l2, l3;
            split1(ax.x, h0, l0); split1(ax.y, h1, l1);
            split1(ax.z, h2, l2); split1(ax.w, h3, l3);
            *(uint2*)&As[s][0][ar][ac * 4] = make_uint2(pack_bf2(h0, h1), pack_bf2(h2, h3));
            *(uint2*)&As[s][1][ar][ac * 4] = make_uint2(pack_bf2(l0, l1), pack_bf2(l2, l3));
            split1(bx.x, h0, l0); split1(bx.y, h1, l1);
            split1(bx.z, h2, l2); split1(bx.w, h3, l3);
            *(uint2*)&Bs[s][0][br][bc] = make_uint2(pack_bf2(h0, h1), pack_bf2(h2, h3));
            *(uint2*)&Bs[s][1][br][bc] = make_uint2(pack_bf2(l0, l1), pack_bf2(l2, l3));
        }
        if (it + 1 < 64) {
            const int k0 = (it + 1) * 16;
            ax = *(const float4*)(X + (size_t)(bm + ar) * 1024 + k0 + ac * 4);
            bx = *(const float4*)(W + (size_t)(k0 + br) * 1024 + bn + bc);
        }
        __syncthreads();

        const __nv_bfloat16* Ah = &As[s][0][0][0];
        const __nv_bfloat16* Al = &As[s][1][0][0];
        uint32_t af[2][2][4];
#pragma unroll
        for (int mt = 0; mt < 2; mt++) {
            const int r = wm * 32 + mt * 16;
#pragma unroll
            for (int hl = 0; hl < 2; hl++) {
                const __nv_bfloat16* P = hl ? Al : Ah;
                af[mt][hl][0] = *(const uint32_t*)(P + (r + g) * 24 + 2 * t);
                af[mt][hl][1] = *(const uint32_t*)(P + (r + g + 8) * 24 + 2 * t);
                af[mt][hl][2] = *(const uint32_t*)(P + (r + g) * 24 + 2 * t + 8);
                af[mt][hl][3] = *(const uint32_t*)(P + (r + g + 8) * 24 + 2 * t + 8);
            }
        }
        const unsigned short* Bh = (const unsigned short*)&Bs[s][0][0][0];
        const unsigned short* Bl = (const unsigned short*)&Bs[s][1][0][0];
        uint32_t bfr[4][2][2];
#pragma unroll
        for (int nt = 0; nt < 4; nt++) {
            const int n = wn * 32 + nt * 8 + g;
#pragma unroll
            for (int hl = 0; hl < 2; hl++) {
                const unsigned short* P = hl ? Bl : Bh;
                bfr[nt][hl][0] = (uint32_t)P[(2 * t) * 136 + n] |
                                 ((uint32_t)P[(2 * t + 1) * 136 + n] << 16);
                bfr[nt][hl][1] = (uint32_t)P[(2 * t + 8) * 136 + n] |
                                 ((uint32_t)P[(2 * t + 9) * 136 + n] << 16);
            }
        }
#pragma unroll
        for (int mt = 0; mt < 2; mt++)
#pragma unroll
            for (int nt = 0; nt < 4; nt++) {
                mma_bf16(acc[mt][nt], af[mt][0], bfr[nt][0]);
                mma_bf16(acc[mt][nt], af[mt][0], bfr[nt][1]);
                mma_bf16(acc[mt][nt], af[mt][1], bfr[nt][0]);
            }
    }

#pragma unroll
    for (int mt = 0; mt < 2; mt++) {
        const int row0 = bm + wm * 32 + mt * 16 + g;
#pragma unroll
        for (int nt = 0; nt < 4; nt++) {
            const int col = bn + wn * 32 + nt * 8 + 2 * t;
            const float b0 = Bi[col], b1 = Bi[col + 1];
            const float v00 = acc[mt][nt][0] + b0, v01 = acc[mt][nt][1] + b1;
            const float v10 = acc[mt][nt][2] + b0, v11 = acc[mt][nt][3] + b1;
            if (DENSE) {
                *(float2*)(OUT + (size_t)row0 * 1024 + col)       = make_float2(v00, v01);
                *(float2*)(OUT + (size_t)(row0 + 8) * 1024 + col) = make_float2(v10, v11);
            } else {
                const int hh = col >> 6, dc = col & 63;
                const int b_ = row0 >> 11;
                const size_t o0 = (((size_t)b_ * 16 + hh) * 2048 + (row0 & 2047)) * 64 + dc;
                const size_t o1 = (((size_t)b_ * 16 + hh) * 2048 + ((row0 + 8) & 2047)) * 64 + dc;
                __nv_bfloat16 h0, l0, h1, l1;
                split1(v00, h0, l0); split1(v01, h1, l1);
                *(uint32_t*)&Hd[o0] = pack_bf2(h0, h1);
                *(uint32_t*)&Ld[o0] = pack_bf2(l0, l1);
                split1(v10, h0, l0); split1(v11, h1, l1);
                *(uint32_t*)&Hd[o1] = pack_bf2(h0, h1);
                *(uint32_t*)&Ld[o1] = pack_bf2(l0, l1);
            }
        }
    }
}

// ---------------------------------------------------------------------------
// logits_k: e = exp(0.125*QK^T + mask*-1e9) stored FP16; rowsum += partials.
// ---------------------------------------------------------------------------
__global__ void __launch_bounds__(512, 1)
logits_k(const __nv_bfloat16* __restrict__ Qhi, const __nv_bfloat16* __restrict__ Qlo,
         const __nv_bfloat16* __restrict__ Khi, const __nv_bfloat16* __restrict__ Klo,
         const float* __restrict__ mask, __half* __restrict__ E,
         float* __restrict__ rowsum)
{
    extern __shared__ __nv_bfloat16 dyn[];
    __shared__ float red[128];

    const int bh = blockIdx.z, b = bh >> 4;
    const int bm = blockIdx.y * 128, bn = blockIdx.x * 128;
    const int tid = threadIdx.x, lane = tid & 31, warp = tid >> 5;
    const int g = lane >> 2, t = lane & 3;
    const int wm = warp >> 2, wn = warp & 3;

    if (tid < 128) red[tid] = 0.f;

#pragma unroll
    for (int j = 0; j < 8; j++) {
        const int id = j * 512 + tid;
        const int p = id >> 10, r = (id >> 3) & 127, ch = id & 7;
        const __nv_bfloat16* src =
            p == 0 ? Qhi + ((size_t)bh * 2048 + bm + r) * 64 + ch * 8 :
            p == 1 ? Qlo + ((size_t)bh * 2048 + bm + r) * 64 + ch * 8 :
            p == 2 ? Khi + ((size_t)bh * 2048 + bn + r) * 64 + ch * 8 :
                     Klo + ((size_t)bh * 2048 + bn + r) * 64 + ch * 8;
        cp16(dyn + p * 9216 + r * 72 + ch * 8, src);
    }
    CP_COMMIT(); CP_WAIT(0);
    __syncthreads();

    const __nv_bfloat16* Qh_ = dyn;
    const __nv_bfloat16* Ql_ = dyn + 9216;
    const __nv_bfloat16* Kh_ = dyn + 18432;
    const __nv_bfloat16* Kl_ = dyn + 27648;

    float acc[2][4][4] = {};
#pragma unroll
    for (int kc = 0; kc < 64; kc += 16) {
        uint32_t af[2][2][4];
#pragma unroll
        for (int mt = 0; mt < 2; mt++) {
            const int r = wm * 32 + mt * 16;
#pragma unroll
            for (int hl = 0; hl < 2; hl++) {
                const __nv_bfloat16* P = hl ? Ql_ : Qh_;
                af[mt][hl][0] = *(const uint32_t*)(P + (r + g) * 72 + kc + 2 * t);
                af[mt][hl][1] = *(const uint32_t*)(P + (r + g + 8) * 72 + kc + 2 * t);
                af[mt][hl][2] = *(const uint32_t*)(P + (r + g) * 72 + kc + 2 * t + 8);
                af[mt][hl][3] = *(const uint32_t*)(P + (r + g + 8) * 72 + kc + 2 * t + 8);
            }
        }
        uint32_t bfr[4][2][2];
#pragma unroll
        for (int nt = 0; nt < 4; nt++) {
            const int n = wn * 32 + nt * 8 + g;
#pragma unroll
            for (int hl = 0; hl < 2; hl++) {
                const __nv_bfloat16* P = hl ? Kl_ : Kh_;
                bfr[nt][hl][0] = *(const uint32_t*)(P + n * 72 + kc + 2 * t);
                bfr[nt][hl][1] = *(const uint32_t*)(P + n * 72 + kc + 2 * t + 8);
            }
        }
#pragma unroll
        for (int mt = 0; mt < 2; mt++)
#pragma unroll
            for (int nt = 0; nt < 4; nt++) {
                mma_bf16(acc[mt][nt], af[mt][0], bfr[nt][0]);
                mma_bf16(acc[mt][nt], af[mt][0], bfr[nt][1]);
                mma_bf16(acc[mt][nt], af[mt][1], bfr[nt][0]);
            }
    }

    float rs[2][2] = {};
#pragma unroll
    for (int mt = 0; mt < 2; mt++) {
        const int rl0 = wm * 32 + mt * 16 + g;
#pragma unroll
        for (int nt = 0; nt < 4; nt++) {
            const int cl = wn * 32 + nt * 8 + 2 * t;
            const int gc = bn + cl;
            const float mk0 = mask[(size_t)b * 2048 + gc] * -1e9f;
            const float mk1 = mask[(size_t)b * 2048 + gc + 1] * -1e9f;
            const float e00 = __expf(acc[mt][nt][0] * 0.125f + mk0);
            const float e01 = __expf(acc[mt][nt][1] * 0.125f + mk1);
            const float e10 = __expf(acc[mt][nt][2] * 0.125f + mk0);
            const float e11 = __expf(acc[mt][nt][3] * 0.125f + mk1);
            __stcs((__half2*)(E + ((size_t)bh * 2048 + bm + rl0) * 2048 + gc),
                   __floats2half2_rn(e00, e01));
            __stcs((__half2*)(E + ((size_t)bh * 2048 + bm + rl0 + 8) * 2048 + gc),
                   __floats2half2_rn(e10, e11));
            rs[mt][0] += e00 + e01;
            rs[mt][1] += e10 + e11;
        }
    }
#pragma unroll
    for (int mt = 0; mt < 2; mt++)
#pragma unroll
        for (int hf = 0; hf < 2; hf++) {
            float v = rs[mt][hf];
            v += __shfl_xor_sync(0xffffffffu, v, 1);
            v += __shfl_xor_sync(0xffffffffu, v, 2);
            if (t == 0) atomicAdd(&red[wm * 32 + mt * 16 + hf * 8 + g], v);
        }
    __syncthreads();
    if (tid < 128) atomicAdd(&rowsum[(size_t)bh * 2048 + bm + tid], red[tid]);
}

// ---------------------------------------------------------------------------
// ctx_k: read e (fp16, streaming), normalize, write fp32 attn to d_out
// (pure store), split P to bf16 hi/lo, ctx = P @ V via MMA.
// 256 thr, CTA 128x64 per bh, BK=16.
// ---------------------------------------------------------------------------
__global__ void __launch_bounds__(256, 2)
ctx_k(const __half* __restrict__ E,
      const __nv_bfloat16* __restrict__ Vhi, const __nv_bfloat16* __restrict__ Vlo,
      const float* __restrict__ rowsum, float* __restrict__ attn,
      float* __restrict__ ctx)
{
    __shared__ __align__(16) __nv_bfloat16 As[2][2][128][24];
    __shared__ __align__(16) __nv_bfloat16 Vs[2][2][16][72];

    const int bh = blockIdx.z, b = bh >> 4, h = bh & 15;
    const int bm = blockIdx.x * 128;
    const int tid = threadIdx.x, lane = tid & 31, warp = tid >> 5;
    const int g = lane >> 2, t = lane & 3;
    const int wm = warp >> 1, wn = warp & 1;

    const int lr = tid >> 1, lc = tid & 1;   // row 0..127, 8-col chunk 0..1
    const float inv = 1.f / rowsum[(size_t)bh * 2048 + bm + lr];
    const __half* Erow = E + ((size_t)bh * 2048 + bm + lr) * 2048 + lc * 8;
    float* Arow = attn + ((size_t)bh * 2048 + bm + lr) * 2048 + lc * 8;

    const int vp = tid >> 7, vid = tid & 127, vkr = vid >> 3, vch = vid & 7;
    const __nv_bfloat16* Vsrc = vp ? Vlo : Vhi;

    uint4 ev = __ldcs((const uint4*)Erow);
    cp16(&Vs[0][vp][vkr][vch * 8], Vsrc + ((size_t)bh * 2048 + vkr) * 64 + vch * 8);
    CP_COMMIT();

    float acc[2][4][4] = {};

    for (int it = 0; it < 128; ++it) {
        const int s = it & 1;
        // unpack 8 halves, normalize
        float p[8];
        {
            const __half2* h2 = (const __half2*)&ev;
#pragma unroll
            for (int q = 0; q < 4; q++) {
                float2 f = __half22float2(h2[q]);
                p[2 * q]     = f.x * inv;
                p[2 * q + 1] = f.y * inv;
            }
        }
        __stcs((float4*)(Arow + it * 16),     make_float4(p[0], p[1], p[2], p[3]));
        __stcs((float4*)(Arow + it * 16 + 4), make_float4(p[4], p[5], p[6], p[7]));
        {
            __nv_bfloat16 hv[8], lv[8];
#pragma unroll
            for (int q = 0; q < 8; q++) split1(p[q], hv[q], lv[q]);
            *(uint4*)&As[s][0][lr][lc * 8] =
                make_uint4(pack_bf2(hv[0], hv[1]), pack_bf2(hv[2], hv[3]),
                           pack_bf2(hv[4], hv[5]), pack_bf2(hv[6], hv[7]));
            *(uint4*)&As[s][1][lr][lc * 8] =
                make_uint4(pack_bf2(lv[0], lv[1]), pack_bf2(lv[2], lv[3]),
                           pack_bf2(lv[4], lv[5]), pack_bf2(lv[6], lv[7]));
        }
        if (it + 1 < 128)
            ev = __ldcs((const uint4*)(Erow + (it + 1) * 16));
        CP_WAIT(0);
        __syncthreads();
        if (it + 1 < 128) {
            const int k0 = (it + 1) * 16;
            cp16(&Vs[s ^ 1][vp][vkr][vch * 8],
                 Vsrc + ((size_t)bh * 2048 + k0 + vkr) * 64 + vch * 8);
            CP_COMMIT();
        }

        const __nv_bfloat16* Ah = &As[s][0][0][0];
        const __nv_bfloat16* Al = &As[s][1][0][0];
        uint32_t af[2][2][4];
#pragma unroll
        for (int mt = 0; mt < 2; mt++) {
            const int r = wm * 32 + mt * 16;
#pragma unroll
            for (int hl = 0; hl < 2; hl++) {
                const __nv_bfloat16* P = hl ? Al : Ah;
                af[mt][hl][0] = *(const uint32_t*)(P + (r + g) * 24 + 2 * t);
                af[mt][hl][1] = *(const uint32_t*)(P + (r + g + 8) * 24 + 2 * t);
                af[mt][hl][2] = *(const uint32_t*)(P + (r + g) * 24 + 2 * t + 8);
                af[mt][hl][3] = *(const uint32_t*)(P + (r + g + 8) * 24 + 2 * t + 8);
            }
        }
        const unsigned short* Bh_ = (const unsigned short*)&Vs[s][0][0][0];
        const unsigned short* Bl_ = (const unsigned short*)&Vs[s][1][0][0];
        uint32_t bfr[4][2][2];
#pragma unroll
        for (int nt = 0; nt < 4; nt++) {
            const int n = wn * 32 + nt * 8 + g;
#pragma unroll
            for (int hl = 0; hl < 2; hl++) {
                const unsigned short* P = hl ? Bl_ : Bh_;
                bfr[nt][hl][0] = (uint32_t)P[(2 * t) * 72 + n] |
                                 ((uint32_t)P[(2 * t + 1) * 72 + n] << 16);
                bfr[nt][hl][1] = (uint32_t)P[(2 * t + 8) * 72 + n] |
                                 ((uint32_t)P[(2 * t + 9) * 72 + n] << 16);
            }
        }
#pragma unroll
        for (int mt = 0; mt < 2; mt++)
#pragma unroll
            for (int nt = 0; nt < 4; nt++) {
                mma_bf16(acc[mt][nt], af[mt][0], bfr[nt][0]);
                mma_bf16(acc[mt][nt], af[mt][0], bfr[nt][1]);
                mma_bf16(acc[mt][nt], af[mt][1], bfr[nt][0]);
            }
    }

#pragma unroll
    for (int mt = 0; mt < 2; mt++) {
        const int row0 = bm + wm * 32 + mt * 16 + g;
#pragma unroll
        for (int nt = 0; nt < 4; nt++) {
            const int col = wn * 32 + nt * 8 + 2 * t;
            *(float2*)(ctx + ((size_t)b * 2048 + row0) * 1024 + h * 64 + col) =
                make_float2(acc[mt][nt][0], acc[mt][nt][1]);
            *(float2*)(ctx + ((size_t)b * 2048 + row0 + 8) * 1024 + h * 64 + col) =
                make_float2(acc[mt][nt][2], acc[mt][nt][3]);
        }
    }
}

// ---------------------------------------------------------------------------
extern "C" void kernel_launch(void* const* d_in, const int* in_sizes, int n_in,
                              void* d_out, int out_size)
{
    const float* q    = (const float*)d_in[0];
    const float* k    = (const float*)d_in[1];
    const float* v    = (const float*)d_in[2];
    const float* mask = (const float*)d_in[3];
    const float* Wq   = (const float*)d_in[4];
    const float* bq   = (const float*)d_in[5];
    const float* Wk   = (const float*)d_in[6];
    const float* bk   = (const float*)d_in[7];
    const float* Wv   = (const float*)d_in[8];
    const float* bv   = (const float*)d_in[9];
    const float* Wo   = (const float*)d_in[10];
    const float* bo   = (const float*)d_in[11];

    float* out  = (float*)d_out;
    float* attn = out + (size_t)BSz * Dd;

    __nv_bfloat16 *Qhi, *Qlo, *Khi, *Klo, *Vhi, *Vlo;
    float *ctxp, *rowsum;
    __half* E;
    cudaGetSymbolAddress((void**)&Qhi, g_Qhi);
    cudaGetSymbolAddress((void**)&Qlo, g_Qlo);
    cudaGetSymbolAddress((void**)&Khi, g_Khi);
    cudaGetSymbolAddress((void**)&Klo, g_Klo);
    cudaGetSymbolAddress((void**)&Vhi, g_Vhi);
    cudaGetSymbolAddress((void**)&Vlo, g_Vlo);
    cudaGetSymbolAddress((void**)&ctxp, g_ctx);
    cudaGetSymbolAddress((void**)&rowsum, g_rowsum);
    cudaGetSymbolAddress((void**)&E, g_e);

    cudaFuncSetAttribute(logits_k, cudaFuncAttributeMaxDynamicSharedMemorySize, 73728);

    zero_k<<<512, 256>>>(rowsum, BH * Ss);

    proj_k<0><<<dim3(8, 64, 3), 512>>>(q, k, v, Wq, Wk, Wv, bq, bk, bv,
                                       Qhi, Qlo, Khi, Klo, Vhi, Vlo, nullptr);

    logits_k<<<dim3(16, 16, 64), 512, 73728>>>(Qhi, Qlo, Khi, Klo, mask, E, rowsum);

    ctx_k<<<dim3(16, 1, 64), 256>>>(E, Vhi, Vlo, rowsum, attn, ctxp);

    proj_k<1><<<dim3(8, 64, 1), 512>>>(ctxp, ctxp, ctxp, Wo, Wo, Wo, bo, bo, bo,
                                       nullptr, nullptr, nullptr, nullptr,
                                       nullptr, nullptr, out);
}

// round 6
// speedup vs baseline: 1.1419x; 1.1393x over previous
#include <cuda_runtime.h>
#include <cuda_bf16.h>
#include <cuda_fp16.h>
#include <cstdint>

#define Ss  2048
#define Dd  1024
#define Hh  16
#define BH  64
#define BSz 8192

// Scratch (__device__ globals; no allocation)
__device__ __nv_bfloat16 g_Qhi[(size_t)BH * Ss * 64];
__device__ __nv_bfloat16 g_Qlo[(size_t)BH * Ss * 64];
__device__ __nv_bfloat16 g_Khi[(size_t)BH * Ss * 64];
__device__ __nv_bfloat16 g_Klo[(size_t)BH * Ss * 64];
__device__ __nv_bfloat16 g_Vhi[(size_t)BH * Ss * 64];
__device__ __nv_bfloat16 g_Vlo[(size_t)BH * Ss * 64];
__device__ float g_ctx[(size_t)BSz * Dd];
__device__ float g_rowsum[(size_t)BH * Ss];
__device__ __half g_e[(size_t)BH * Ss * Ss];   // unnormalized exp(logits), fp16

// ---------------------------------------------------------------------------
__device__ __forceinline__ uint32_t s2u(const void* p) {
    uint32_t a;
    asm("{ .reg .u64 t; cvta.to.shared.u64 t, %1; cvt.u32.u64 %0, t; }"
        : "=r"(a) : "l"(p));
    return a;
}
__device__ __forceinline__ void cp16(void* dst, const void* src) {
    asm volatile("cp.async.cg.shared.global [%0], [%1], 16;"
                 :: "r"(s2u(dst)), "l"(src));
}
#define CP_COMMIT() asm volatile("cp.async.commit_group;")
#define CP_WAIT(n)  asm volatile("cp.async.wait_group %0;" :: "n"(n))

__device__ __forceinline__ void ldsm4(uint32_t r[4], uint32_t a) {
    asm volatile("ldmatrix.sync.aligned.m8n8.x4.shared.b16 {%0,%1,%2,%3}, [%4];"
                 : "=r"(r[0]), "=r"(r[1]), "=r"(r[2]), "=r"(r[3]) : "r"(a));
}
__device__ __forceinline__ void ldsm4t(uint32_t r[4], uint32_t a) {
    asm volatile("ldmatrix.sync.aligned.m8n8.x4.trans.shared.b16 {%0,%1,%2,%3}, [%4];"
                 : "=r"(r[0]), "=r"(r[1]), "=r"(r[2]), "=r"(r[3]) : "r"(a));
}

__device__ __forceinline__ uint32_t pack_bf2(__nv_bfloat16 a, __nv_bfloat16 b) {
    return (uint32_t)__bfloat16_as_ushort(a) | ((uint32_t)__bfloat16_as_ushort(b) << 16);
}
__device__ __forceinline__ void split1(float x, __nv_bfloat16& h, __nv_bfloat16& l) {
    h = __float2bfloat16(x);
    l = __float2bfloat16(x - __bfloat162float(h));
}
__device__ __forceinline__ void mma_bf16(float c[4], const uint32_t a[4], const uint32_t b[2]) {
    asm volatile(
        "mma.sync.aligned.m16n8k16.row.col.f32.bf16.bf16.f32 "
        "{%0,%1,%2,%3}, {%4,%5,%6,%7}, {%8,%9}, {%0,%1,%2,%3};"
        : "+f"(c[0]), "+f"(c[1]), "+f"(c[2]), "+f"(c[3])
        : "r"(a[0]), "r"(a[1]), "r"(a[2]), "r"(a[3]), "r"(b[0]), "r"(b[1]));
}

__global__ void zero_k(float* p, int n) {
    int i = blockIdx.x * 256 + threadIdx.x;
    if (i < n) p[i] = 0.f;
}

// ---------------------------------------------------------------------------
// proj_k: Y = X[8192,1024] @ W[1024,1024] + bias.  z selects matrix set.
// Fragment loads via ldmatrix.
// ---------------------------------------------------------------------------
template <int DENSE>
__global__ void __launch_bounds__(512, 1)
proj_k(const float* __restrict__ X0, const float* __restrict__ X1,
       const float* __restrict__ X2,
       const float* __restrict__ W0, const float* __restrict__ W1,
       const float* __restrict__ W2,
       const float* __restrict__ B0, const float* __restrict__ B1,
       const float* __restrict__ B2,
       __nv_bfloat16* __restrict__ H0, __nv_bfloat16* __restrict__ L0,
       __nv_bfloat16* __restrict__ H1, __nv_bfloat16* __restrict__ L1,
       __nv_bfloat16* __restrict__ H2, __nv_bfloat16* __restrict__ L2,
       float* __restrict__ OUT)
{
    const int z = blockIdx.z;
    const float* X  = z == 0 ? X0 : z == 1 ? X1 : X2;
    const float* W  = z == 0 ? W0 : z == 1 ? W1 : W2;
    const float* Bi = z == 0 ? B0 : z == 1 ? B1 : B2;
    __nv_bfloat16* Hd = z == 0 ? H0 : z == 1 ? H1 : H2;
    __nv_bfloat16* Ld = z == 0 ? L0 : z == 1 ? L1 : L2;

    __shared__ __align__(16) __nv_bfloat16 As[2][2][128][24];
    __shared__ __align__(16) __nv_bfloat16 Bs[2][2][16][136];

    const int tid = threadIdx.x, lane = tid & 31, warp = tid >> 5;
    const int g = lane >> 2, t = lane & 3;
    const int qd = lane >> 3, rr = lane & 7;     // ldmatrix quad / row
    const int wm = warp >> 2, wn = warp & 3;
    const int bm = blockIdx.y * 128, bn = blockIdx.x * 128;

    const int ar = tid >> 2, ac = tid & 3;
    const int br = tid >> 5, bc = (tid & 31) * 4;

    float acc[2][4][4] = {};

    float4 ax = *(const float4*)(X + (size_t)(bm + ar) * 1024 + ac * 4);
    float4 bx = *(const float4*)(W + (size_t)br * 1024 + bn + bc);

    for (int it = 0; it < 64; ++it) {
        const int s = it & 1;
        {
            __nv_bfloat16 h0, h1, h2, h3, l0, l1, l2, l3;
            split1(ax.x, h0, l0); split1(ax.y, h1, l1);
            split1(ax.z, h2, l2); split1(ax.w, h3, l3);
            *(uint2*)&As[s][0][ar][ac * 4] = make_uint2(pack_bf2(h0, h1), pack_bf2(h2, h3));
            *(uint2*)&As[s][1][ar][ac * 4] = make_uint2(pack_bf2(l0, l1), pack_bf2(l2, l3));
            split1(bx.x, h0, l0); split1(bx.y, h1, l1);
            split1(bx.z, h2, l2); split1(bx.w, h3, l3);
            *(uint2*)&Bs[s][0][br][bc] = make_uint2(pack_bf2(h0, h1), pack_bf2(h2, h3));
            *(uint2*)&Bs[s][1][br][bc] = make_uint2(pack_bf2(l0, l1), pack_bf2(l2, l3));
        }
        if (it + 1 < 64) {
            const int k0 = (it + 1) * 16;
            ax = *(const float4*)(X + (size_t)(bm + ar) * 1024 + k0 + ac * 4);
            bx = *(const float4*)(W + (size_t)(k0 + br) * 1024 + bn + bc);
        }
        __syncthreads();

        // A frags via ldmatrix.x4: matrices (m8 x k8) in order a0,a1,a2,a3
        uint32_t af[2][2][4];
#pragma unroll
        for (int mt = 0; mt < 2; mt++)
#pragma unroll
            for (int hl = 0; hl < 2; hl++)
                ldsm4(af[mt][hl],
                      s2u(&As[s][hl][wm * 32 + mt * 16 + (qd & 1) * 8 + rr][(qd >> 1) * 8]));

        // B frags via ldmatrix.x4.trans: rows k, col block n; covers nt pair
        uint32_t bfr[4][2][2];
#pragma unroll
        for (int np = 0; np < 2; np++)
#pragma unroll
            for (int hl = 0; hl < 2; hl++) {
                uint32_t bt[4];
                ldsm4t(bt, s2u(&Bs[s][hl][(qd & 1) * 8 + rr]
                                        [wn * 32 + np * 16 + (qd >> 1) * 8]));
                bfr[np * 2][hl][0]     = bt[0];
                bfr[np * 2][hl][1]     = bt[1];
                bfr[np * 2 + 1][hl][0] = bt[2];
                bfr[np * 2 + 1][hl][1] = bt[3];
            }
#pragma unroll
        for (int mt = 0; mt < 2; mt++)
#pragma unroll
            for (int nt = 0; nt < 4; nt++) {
                mma_bf16(acc[mt][nt], af[mt][0], bfr[nt][0]);
                mma_bf16(acc[mt][nt], af[mt][0], bfr[nt][1]);
                mma_bf16(acc[mt][nt], af[mt][1], bfr[nt][0]);
            }
    }

#pragma unroll
    for (int mt = 0; mt < 2; mt++) {
        const int row0 = bm + wm * 32 + mt * 16 + g;
#pragma unroll
        for (int nt = 0; nt < 4; nt++) {
            const int col = bn + wn * 32 + nt * 8 + 2 * t;
            const float b0 = Bi[col], b1 = Bi[col + 1];
            const float v00 = acc[mt][nt][0] + b0, v01 = acc[mt][nt][1] + b1;
            const float v10 = acc[mt][nt][2] + b0, v11 = acc[mt][nt][3] + b1;
            if (DENSE) {
                *(float2*)(OUT + (size_t)row0 * 1024 + col)       = make_float2(v00, v01);
                *(float2*)(OUT + (size_t)(row0 + 8) * 1024 + col) = make_float2(v10, v11);
            } else {
                const int hh = col >> 6, dc = col & 63;
                const int b_ = row0 >> 11;
                const size_t o0 = (((size_t)b_ * 16 + hh) * 2048 + (row0 & 2047)) * 64 + dc;
                const size_t o1 = (((size_t)b_ * 16 + hh) * 2048 + ((row0 + 8) & 2047)) * 64 + dc;
                __nv_bfloat16 h0, l0, h1, l1;
                split1(v00, h0, l0); split1(v01, h1, l1);
                *(uint32_t*)&Hd[o0] = pack_bf2(h0, h1);
                *(uint32_t*)&Ld[o0] = pack_bf2(l0, l1);
                split1(v10, h0, l0); split1(v11, h1, l1);
                *(uint32_t*)&Hd[o1] = pack_bf2(h0, h1);
                *(uint32_t*)&Ld[o1] = pack_bf2(l0, l1);
            }
        }
    }
}

// ---------------------------------------------------------------------------
// logits_k: e = exp(0.125*QK^T + mask*-1e9) stored FP16; rowsum += partials.
// Fragment loads via ldmatrix.
// ---------------------------------------------------------------------------
__global__ void __launch_bounds__(512, 1)
logits_k(const __nv_bfloat16* __restrict__ Qhi, const __nv_bfloat16* __restrict__ Qlo,
         const __nv_bfloat16* __restrict__ Khi, const __nv_bfloat16* __restrict__ Klo,
         const float* __restrict__ mask, __half* __restrict__ E,
         float* __restrict__ rowsum)
{
    extern __shared__ __nv_bfloat16 dyn[];
    __shared__ float red[128];

    const int bh = blockIdx.z, b = bh >> 4;
    const int bm = blockIdx.y * 128, bn = blockIdx.x * 128;
    const int tid = threadIdx.x, lane = tid & 31, warp = tid >> 5;
    const int g = lane >> 2, t = lane & 3;
    const int qd = lane >> 3, rr = lane & 7;
    const int wm = warp >> 2, wn = warp & 3;

    if (tid < 128) red[tid] = 0.f;

#pragma unroll
    for (int j = 0; j < 8; j++) {
        const int id = j * 512 + tid;
        const int p = id >> 10, r = (id >> 3) & 127, ch = id & 7;
        const __nv_bfloat16* src =
            p == 0 ? Qhi + ((size_t)bh * 2048 + bm + r) * 64 + ch * 8 :
            p == 1 ? Qlo + ((size_t)bh * 2048 + bm + r) * 64 + ch * 8 :
            p == 2 ? Khi + ((size_t)bh * 2048 + bn + r) * 64 + ch * 8 :
                     Klo + ((size_t)bh * 2048 + bn + r) * 64 + ch * 8;
        cp16(dyn + p * 9216 + r * 72 + ch * 8, src);
    }
    CP_COMMIT(); CP_WAIT(0);
    __syncthreads();

    float acc[2][4][4] = {};
#pragma unroll
    for (int kc = 0; kc < 64; kc += 16) {
        uint32_t af[2][2][4];
#pragma unroll
        for (int mt = 0; mt < 2; mt++)
#pragma unroll
            for (int hl = 0; hl < 2; hl++)
                ldsm4(af[mt][hl],
                      s2u(dyn + hl * 9216 +
                          (wm * 32 + mt * 16 + (qd & 1) * 8 + rr) * 72 +
                          kc + (qd >> 1) * 8));

        // K side: row-major [kv][dh] == B col-major; plain ldmatrix covering nt pair
        uint32_t bfr[4][2][2];
#pragma unroll
        for (int np = 0; np < 2; np++)
#pragma unroll
            for (int hl = 0; hl < 2; hl++) {
                uint32_t bt[4];
                ldsm4(bt, s2u(dyn + 18432 + hl * 9216 +
                              (wn * 32 + np * 16 + (qd >> 1) * 8 + rr) * 72 +
                              kc + (qd & 1) * 8));
                bfr[np * 2][hl][0]     = bt[0];
                bfr[np * 2][hl][1]     = bt[1];
                bfr[np * 2 + 1][hl][0] = bt[2];
                bfr[np * 2 + 1][hl][1] = bt[3];
            }
#pragma unroll
        for (int mt = 0; mt < 2; mt++)
#pragma unroll
            for (int nt = 0; nt < 4; nt++) {
                mma_bf16(acc[mt][nt], af[mt][0], bfr[nt][0]);
                mma_bf16(acc[mt][nt], af[mt][0], bfr[nt][1]);
                mma_bf16(acc[mt][nt], af[mt][1], bfr[nt][0]);
            }
    }

    float rs[2][2] = {};
#pragma unroll
    for (int mt = 0; mt < 2; mt++) {
        const int rl0 = wm * 32 + mt * 16 + g;
#pragma unroll
        for (int nt = 0; nt < 4; nt++) {
            const int cl = wn * 32 + nt * 8 + 2 * t;
            const int gc = bn + cl;
            const float mk0 = mask[(size_t)b * 2048 + gc] * -1e9f;
            const float mk1 = mask[(size_t)b * 2048 + gc + 1] * -1e9f;
            const float e00 = __expf(acc[mt][nt][0] * 0.125f + mk0);
            const float e01 = __expf(acc[mt][nt][1] * 0.125f + mk1);
            const float e10 = __expf(acc[mt][nt][2] * 0.125f + mk0);
            const float e11 = __expf(acc[mt][nt][3] * 0.125f + mk1);
            __stcs((__half2*)(E + ((size_t)bh * 2048 + bm + rl0) * 2048 + gc),
                   __floats2half2_rn(e00, e01));
            __stcs((__half2*)(E + ((size_t)bh * 2048 + bm + rl0 + 8) * 2048 + gc),
                   __floats2half2_rn(e10, e11));
            rs[mt][0] += e00 + e01;
            rs[mt][1] += e10 + e11;
        }
    }
#pragma unroll
    for (int mt = 0; mt < 2; mt++)
#pragma unroll
        for (int hf = 0; hf < 2; hf++) {
            float v = rs[mt][hf];
            v += __shfl_xor_sync(0xffffffffu, v, 1);
            v += __shfl_xor_sync(0xffffffffu, v, 2);
            if (t == 0) atomicAdd(&red[wm * 32 + mt * 16 + hf * 8 + g], v);
        }
    __syncthreads();
    if (tid < 128) atomicAdd(&rowsum[(size_t)bh * 2048 + bm + tid], red[tid]);
}

// ---------------------------------------------------------------------------
// ctx_k: read e (fp16, streaming), normalize, write fp32 attn to d_out,
// split P to bf16 hi/lo, ctx = P @ V via MMA.  Fragment loads via ldmatrix.
// ---------------------------------------------------------------------------
__global__ void __launch_bounds__(256, 2)
ctx_k(const __half* __restrict__ E,
      const __nv_bfloat16* __restrict__ Vhi, const __nv_bfloat16* __restrict__ Vlo,
      const float* __restrict__ rowsum, float* __restrict__ attn,
      float* __restrict__ ctx)
{
    __shared__ __align__(16) __nv_bfloat16 As[2][2][128][24];
    __shared__ __align__(16) __nv_bfloat16 Vs[2][2][16][72];

    const int bh = blockIdx.z, b = bh >> 4, h = bh & 15;
    const int bm = blockIdx.x * 128;
    const int tid = threadIdx.x, lane = tid & 31, warp = tid >> 5;
    const int g = lane >> 2, t = lane & 3;
    const int qd = lane >> 3, rr = lane & 7;
    const int wm = warp >> 1, wn = warp & 1;

    const int lr = tid >> 1, lc = tid & 1;   // row 0..127, 8-col chunk 0..1
    const float inv = 1.f / rowsum[(size_t)bh * 2048 + bm + lr];
    const __half* Erow = E + ((size_t)bh * 2048 + bm + lr) * 2048 + lc * 8;
    float* Arow = attn + ((size_t)bh * 2048 + bm + lr) * 2048 + lc * 8;

    const int vp = tid >> 7, vid = tid & 127, vkr = vid >> 3, vch = vid & 7;
    const __nv_bfloat16* Vsrc = vp ? Vlo : Vhi;

    uint4 ev = __ldcs((const uint4*)Erow);
    cp16(&Vs[0][vp][vkr][vch * 8], Vsrc + ((size_t)bh * 2048 + vkr) * 64 + vch * 8);
    CP_COMMIT();

    float acc[2][4][4] = {};

    for (int it = 0; it < 128; ++it) {
        const int s = it & 1;
        float p[8];
        {
            const __half2* h2 = (const __half2*)&ev;
#pragma unroll
            for (int q = 0; q < 4; q++) {
                float2 f = __half22float2(h2[q]);
                p[2 * q]     = f.x * inv;
                p[2 * q + 1] = f.y * inv;
            }
        }
        __stcs((float4*)(Arow + it * 16),     make_float4(p[0], p[1], p[2], p[3]));
        __stcs((float4*)(Arow + it * 16 + 4), make_float4(p[4], p[5], p[6], p[7]));
        {
            __nv_bfloat16 hv[8], lv[8];
#pragma unroll
            for (int q = 0; q < 8; q++) split1(p[q], hv[q], lv[q]);
            *(uint4*)&As[s][0][lr][lc * 8] =
                make_uint4(pack_bf2(hv[0], hv[1]), pack_bf2(hv[2], hv[3]),
                           pack_bf2(hv[4], hv[5]), pack_bf2(hv[6], hv[7]));
            *(uint4*)&As[s][1][lr][lc * 8] =
                make_uint4(pack_bf2(lv[0], lv[1]), pack_bf2(lv[2], lv[3]),
                           pack_bf2(lv[4], lv[5]), pack_bf2(lv[6], lv[7]));
        }
        if (it + 1 < 128)
            ev = __ldcs((const uint4*)(Erow + (it + 1) * 16));
        CP_WAIT(0);
        __syncthreads();
        if (it + 1 < 128) {
            const int k0 = (it + 1) * 16;
            cp16(&Vs[s ^ 1][vp][vkr][vch * 8],
                 Vsrc + ((size_t)bh * 2048 + k0 + vkr) * 64 + vch * 8);
            CP_COMMIT();
        }

        uint32_t af[2][2][4];
#pragma unroll
        for (int mt = 0; mt < 2; mt++)
#pragma unroll
            for (int hl = 0; hl < 2; hl++)
                ldsm4(af[mt][hl],
                      s2u(&As[s][hl][wm * 32 + mt * 16 + (qd & 1) * 8 + rr][(qd >> 1) * 8]));

        uint32_t bfr[4][2][2];
#pragma unroll
        for (int np = 0; np < 2; np++)
#pragma unroll
            for (int hl = 0; hl < 2; hl++) {
                uint32_t bt[4];
                ldsm4t(bt, s2u(&Vs[s][hl][(qd & 1) * 8 + rr]
                                        [wn * 32 + np * 16 + (qd >> 1) * 8]));
                bfr[np * 2][hl][0]     = bt[0];
                bfr[np * 2][hl][1]     = bt[1];
                bfr[np * 2 + 1][hl][0] = bt[2];
                bfr[np * 2 + 1][hl][1] = bt[3];
            }
#pragma unroll
        for (int mt = 0; mt < 2; mt++)
#pragma unroll
            for (int nt = 0; nt < 4; nt++) {
                mma_bf16(acc[mt][nt], af[mt][0], bfr[nt][0]);
                mma_bf16(acc[mt][nt], af[mt][0], bfr[nt][1]);
                mma_bf16(acc[mt][nt], af[mt][1], bfr[nt][0]);
            }
    }

#pragma unroll
    for (int mt = 0; mt < 2; mt++) {
        const int row0 = bm + wm * 32 + mt * 16 + g;
#pragma unroll
        for (int nt = 0; nt < 4; nt++) {
            const int col = wn * 32 + nt * 8 + 2 * t;
            *(float2*)(ctx + ((size_t)b * 2048 + row0) * 1024 + h * 64 + col) =
                make_float2(acc[mt][nt][0], acc[mt][nt][1]);
            *(float2*)(ctx + ((size_t)b * 2048 + row0 + 8) * 1024 + h * 64 + col) =
                make_float2(acc[mt][nt][2], acc[mt][nt][3]);
        }
    }
}

// ---------------------------------------------------------------------------
extern "C" void kernel_launch(void* const* d_in, const int* in_sizes, int n_in,
                              void* d_out, int out_size)
{
    const float* q    = (const float*)d_in[0];
    const float* k    = (const float*)d_in[1];
    const float* v    = (const float*)d_in[2];
    const float* mask = (const float*)d_in[3];
    const float* Wq   = (const float*)d_in[4];
    const float* bq   = (const float*)d_in[5];
    const float* Wk   = (const float*)d_in[6];
    const float* bk   = (const float*)d_in[7];
    const float* Wv   = (const float*)d_in[8];
    const float* bv   = (const float*)d_in[9];
    const float* Wo   = (const float*)d_in[10];
    const float* bo   = (const float*)d_in[11];

    float* out  = (float*)d_out;
    float* attn = out + (size_t)BSz * Dd;

    __nv_bfloat16 *Qhi, *Qlo, *Khi, *Klo, *Vhi, *Vlo;
    float *ctxp, *rowsum;
    __half* E;
    cudaGetSymbolAddress((void**)&Qhi, g_Qhi);
    cudaGetSymbolAddress((void**)&Qlo, g_Qlo);
    cudaGetSymbolAddress((void**)&Khi, g_Khi);
    cudaGetSymbolAddress((void**)&Klo, g_Klo);
    cudaGetSymbolAddress((void**)&Vhi, g_Vhi);
    cudaGetSymbolAddress((void**)&Vlo, g_Vlo);
    cudaGetSymbolAddress((void**)&ctxp, g_ctx);
    cudaGetSymbolAddress((void**)&rowsum, g_rowsum);
    cudaGetSymbolAddress((void**)&E, g_e);

    cudaFuncSetAttribute(logits_k, cudaFuncAttributeMaxDynamicSharedMemorySize, 73728);

    zero_k<<<512, 256>>>(rowsum, BH * Ss);

    proj_k<0><<<dim3(8, 64, 3), 512>>>(q, k, v, Wq, Wk, Wv, bq, bk, bv,
                                       Qhi, Qlo, Khi, Klo, Vhi, Vlo, nullptr);

    logits_k<<<dim3(16, 16, 64), 512, 73728>>>(Qhi, Qlo, Khi, Klo, mask, E, rowsum);

    ctx_k<<<dim3(16, 1, 64), 256>>>(E, Vhi, Vlo, rowsum, attn, ctxp);

    proj_k<1><<<dim3(8, 64, 1), 512>>>(ctxp, ctxp, ctxp, Wo, Wo, Wo, bo, bo, bo,
                                       nullptr, nullptr, nullptr, nullptr,
                                       nullptr, nullptr, out);
}

// round 7
// speedup vs baseline: 1.1573x; 1.0135x over previous
#include <cuda_runtime.h>
#include <cuda_bf16.h>
#include <cuda_fp16.h>
#include <cstdint>

#define Ss  2048
#define Dd  1024
#define Hh  16
#define BH  64
#define BSz 8192

// Scratch (__device__ globals; no allocation)
__device__ __nv_bfloat16 g_Qhi[(size_t)BH * Ss * 64];
__device__ __nv_bfloat16 g_Qlo[(size_t)BH * Ss * 64];
__device__ __nv_bfloat16 g_Khi[(size_t)BH * Ss * 64];
__device__ __nv_bfloat16 g_Klo[(size_t)BH * Ss * 64];
__device__ __nv_bfloat16 g_Vhi[(size_t)BH * Ss * 64];   // holds fp16 bits for V
__device__ __nv_bfloat16 g_Vlo[(size_t)BH * Ss * 64];   // holds fp16 bits for V
__device__ float g_ctx[(size_t)BSz * Dd];
__device__ float g_rowsum[(size_t)BH * Ss];
__device__ __half g_e[(size_t)BH * Ss * Ss];   // unnormalized exp(logits), fp16

// ---------------------------------------------------------------------------
__device__ __forceinline__ uint32_t s2u(const void* p) {
    uint32_t a;
    asm("{ .reg .u64 t; cvta.to.shared.u64 t, %1; cvt.u32.u64 %0, t; }"
        : "=r"(a) : "l"(p));
    return a;
}
__device__ __forceinline__ void cp16(void* dst, const void* src) {
    asm volatile("cp.async.cg.shared.global [%0], [%1], 16;"
                 :: "r"(s2u(dst)), "l"(src));
}
#define CP_COMMIT() asm volatile("cp.async.commit_group;")
#define CP_WAIT(n)  asm volatile("cp.async.wait_group %0;" :: "n"(n))

__device__ __forceinline__ void ldsm4(uint32_t r[4], uint32_t a) {
    asm volatile("ldmatrix.sync.aligned.m8n8.x4.shared.b16 {%0,%1,%2,%3}, [%4];"
                 : "=r"(r[0]), "=r"(r[1]), "=r"(r[2]), "=r"(r[3]) : "r"(a));
}
__device__ __forceinline__ void ldsm4t(uint32_t r[4], uint32_t a) {
    asm volatile("ldmatrix.sync.aligned.m8n8.x4.trans.shared.b16 {%0,%1,%2,%3}, [%4];"
                 : "=r"(r[0]), "=r"(r[1]), "=r"(r[2]), "=r"(r[3]) : "r"(a));
}

__device__ __forceinline__ uint32_t pack_bf2(__nv_bfloat16 a, __nv_bfloat16 b) {
    return (uint32_t)__bfloat16_as_ushort(a) | ((uint32_t)__bfloat16_as_ushort(b) << 16);
}
__device__ __forceinline__ uint32_t pack_hf2(__half a, __half b) {
    return (uint32_t)__half_as_ushort(a) | ((uint32_t)__half_as_ushort(b) << 16);
}
__device__ __forceinline__ void split1(float x, __nv_bfloat16& h, __nv_bfloat16& l) {
    h = __float2bfloat16(x);
    l = __float2bfloat16(x - __bfloat162float(h));
}
__device__ __forceinline__ void splith(float x, __half& h, __half& l) {
    h = __float2half_rn(x);
    l = __float2half_rn(x - __half2float(h));
}
__device__ __forceinline__ void mma_bf16(float c[4], const uint32_t a[4], const uint32_t b[2]) {
    asm volatile(
        "mma.sync.aligned.m16n8k16.row.col.f32.bf16.bf16.f32 "
        "{%0,%1,%2,%3}, {%4,%5,%6,%7}, {%8,%9}, {%0,%1,%2,%3};"
        : "+f"(c[0]), "+f"(c[1]), "+f"(c[2]), "+f"(c[3])
        : "r"(a[0]), "r"(a[1]), "r"(a[2]), "r"(a[3]), "r"(b[0]), "r"(b[1]));
}
__device__ __forceinline__ void mma_f16(float c[4], const uint32_t a[4], const uint32_t b[2]) {
    asm volatile(
        "mma.sync.aligned.m16n8k16.row.col.f32.f16.f16.f32 "
        "{%0,%1,%2,%3}, {%4,%5,%6,%7}, {%8,%9}, {%0,%1,%2,%3};"
        : "+f"(c[0]), "+f"(c[1]), "+f"(c[2]), "+f"(c[3])
        : "r"(a[0]), "r"(a[1]), "r"(a[2]), "r"(a[3]), "r"(b[0]), "r"(b[1]));
}

__global__ void zero_k(float* p, int n) {
    int i = blockIdx.x * 256 + threadIdx.x;
    if (i < n) p[i] = 0.f;
}

// ---------------------------------------------------------------------------
// proj_k: Y = X[8192,1024] @ W[1024,1024] + bias.  z selects matrix set.
// z==2 (V) writes fp16 hi/lo (for fp16 MMA in ctx); z==0,1 write bf16 hi/lo.
// ---------------------------------------------------------------------------
template <int DENSE>
__global__ void __launch_bounds__(512, 1)
proj_k(const float* __restrict__ X0, const float* __restrict__ X1,
       const float* __restrict__ X2,
       const float* __restrict__ W0, const float* __restrict__ W1,
       const float* __restrict__ W2,
       const float* __restrict__ B0, const float* __restrict__ B1,
       const float* __restrict__ B2,
       __nv_bfloat16* __restrict__ H0, __nv_bfloat16* __restrict__ L0,
       __nv_bfloat16* __restrict__ H1, __nv_bfloat16* __restrict__ L1,
       __nv_bfloat16* __restrict__ H2, __nv_bfloat16* __restrict__ L2,
       float* __restrict__ OUT)
{
    const int z = blockIdx.z;
    const float* X  = z == 0 ? X0 : z == 1 ? X1 : X2;
    const float* W  = z == 0 ? W0 : z == 1 ? W1 : W2;
    const float* Bi = z == 0 ? B0 : z == 1 ? B1 : B2;
    __nv_bfloat16* Hd = z == 0 ? H0 : z == 1 ? H1 : H2;
    __nv_bfloat16* Ld = z == 0 ? L0 : z == 1 ? L1 : L2;

    __shared__ __align__(16) __nv_bfloat16 As[2][2][128][24];
    __shared__ __align__(16) __nv_bfloat16 Bs[2][2][16][136];

    const int tid = threadIdx.x, lane = tid & 31, warp = tid >> 5;
    const int g = lane >> 2, t = lane & 3;
    const int qd = lane >> 3, rr = lane & 7;
    const int wm = warp >> 2, wn = warp & 3;
    const int bm = blockIdx.y * 128, bn = blockIdx.x * 128;

    const int ar = tid >> 2, ac = tid & 3;
    const int br = tid >> 5, bc = (tid & 31) * 4;

    float acc[2][4][4] = {};

    float4 ax = *(const float4*)(X + (size_t)(bm + ar) * 1024 + ac * 4);
    float4 bx = *(const float4*)(W + (size_t)br * 1024 + bn + bc);

    for (int it = 0; it < 64; ++it) {
        const int s = it & 1;
        {
            __nv_bfloat16 h0, h1, h2, h3, l0, l1, l2, l3;
            split1(ax.x, h0, l0); split1(ax.y, h1, l1);
            split1(ax.z, h2, l2); split1(ax.w, h3, l3);
            *(uint2*)&As[s][0][ar][ac * 4] = make_uint2(pack_bf2(h0, h1), pack_bf2(h2, h3));
            *(uint2*)&As[s][1][ar][ac * 4] = make_uint2(pack_bf2(l0, l1), pack_bf2(l2, l3));
            split1(bx.x, h0, l0); split1(bx.y, h1, l1);
            split1(bx.z, h2, l2); split1(bx.w, h3, l3);
            *(uint2*)&Bs[s][0][br][bc] = make_uint2(pack_bf2(h0, h1), pack_bf2(h2, h3));
            *(uint2*)&Bs[s][1][br][bc] = make_uint2(pack_bf2(l0, l1), pack_bf2(l2, l3));
        }
        if (it + 1 < 64) {
            const int k0 = (it + 1) * 16;
            ax = *(const float4*)(X + (size_t)(bm + ar) * 1024 + k0 + ac * 4);
            bx = *(const float4*)(W + (size_t)(k0 + br) * 1024 + bn + bc);
        }
        __syncthreads();

        uint32_t af[2][2][4];
#pragma unroll
        for (int mt = 0; mt < 2; mt++)
#pragma unroll
            for (int hl = 0; hl < 2; hl++)
                ldsm4(af[mt][hl],
                      s2u(&As[s][hl][wm * 32 + mt * 16 + (qd & 1) * 8 + rr][(qd >> 1) * 8]));

        uint32_t bfr[4][2][2];
#pragma unroll
        for (int np = 0; np < 2; np++)
#pragma unroll
            for (int hl = 0; hl < 2; hl++) {
                uint32_t bt[4];
                ldsm4t(bt, s2u(&Bs[s][hl][(qd & 1) * 8 + rr]
                                        [wn * 32 + np * 16 + (qd >> 1) * 8]));
                bfr[np * 2][hl][0]     = bt[0];
                bfr[np * 2][hl][1]     = bt[1];
                bfr[np * 2 + 1][hl][0] = bt[2];
                bfr[np * 2 + 1][hl][1] = bt[3];
            }
#pragma unroll
        for (int mt = 0; mt < 2; mt++)
#pragma unroll
            for (int nt = 0; nt < 4; nt++) {
                mma_bf16(acc[mt][nt], af[mt][0], bfr[nt][0]);
                mma_bf16(acc[mt][nt], af[mt][0], bfr[nt][1]);
                mma_bf16(acc[mt][nt], af[mt][1], bfr[nt][0]);
            }
    }

#pragma unroll
    for (int mt = 0; mt < 2; mt++) {
        const int row0 = bm + wm * 32 + mt * 16 + g;
#pragma unroll
        for (int nt = 0; nt < 4; nt++) {
            const int col = bn + wn * 32 + nt * 8 + 2 * t;
            const float b0 = Bi[col], b1 = Bi[col + 1];
            const float v00 = acc[mt][nt][0] + b0, v01 = acc[mt][nt][1] + b1;
            const float v10 = acc[mt][nt][2] + b0, v11 = acc[mt][nt][3] + b1;
            if (DENSE) {
                *(float2*)(OUT + (size_t)row0 * 1024 + col)       = make_float2(v00, v01);
                *(float2*)(OUT + (size_t)(row0 + 8) * 1024 + col) = make_float2(v10, v11);
            } else {
                const int hh = col >> 6, dc = col & 63;
                const int b_ = row0 >> 11;
                const size_t o0 = (((size_t)b_ * 16 + hh) * 2048 + (row0 & 2047)) * 64 + dc;
                const size_t o1 = (((size_t)b_ * 16 + hh) * 2048 + ((row0 + 8) & 2047)) * 64 + dc;
                if (z == 2) {   // V: fp16 hi/lo for fp16 MMA in ctx_k
                    __half h0, l0, h1, l1;
                    splith(v00, h0, l0); splith(v01, h1, l1);
                    *(uint32_t*)&Hd[o0] = pack_hf2(h0, h1);
                    *(uint32_t*)&Ld[o0] = pack_hf2(l0, l1);
                    splith(v10, h0, l0); splith(v11, h1, l1);
                    *(uint32_t*)&Hd[o1] = pack_hf2(h0, h1);
                    *(uint32_t*)&Ld[o1] = pack_hf2(l0, l1);
                } else {        // Q/K: bf16 hi/lo for split-bf16 MMA in logits_k
                    __nv_bfloat16 h0, l0, h1, l1;
                    split1(v00, h0, l0); split1(v01, h1, l1);
                    *(uint32_t*)&Hd[o0] = pack_bf2(h0, h1);
                    *(uint32_t*)&Ld[o0] = pack_bf2(l0, l1);
                    split1(v10, h0, l0); split1(v11, h1, l1);
                    *(uint32_t*)&Hd[o1] = pack_bf2(h0, h1);
                    *(uint32_t*)&Ld[o1] = pack_bf2(l0, l1);
                }
            }
        }
    }
}

// ---------------------------------------------------------------------------
// logits_k: e = exp(0.125*QK^T + mask*-1e9) stored FP16; rowsum += partials.
// ---------------------------------------------------------------------------
__global__ void __launch_bounds__(512, 1)
logits_k(const __nv_bfloat16* __restrict__ Qhi, const __nv_bfloat16* __restrict__ Qlo,
         const __nv_bfloat16* __restrict__ Khi, const __nv_bfloat16* __restrict__ Klo,
         const float* __restrict__ mask, __half* __restrict__ E,
         float* __restrict__ rowsum)
{
    extern __shared__ __nv_bfloat16 dyn[];
    __shared__ float red[128];

    const int bh = blockIdx.z, b = bh >> 4;
    const int bm = blockIdx.y * 128, bn = blockIdx.x * 128;
    const int tid = threadIdx.x, lane = tid & 31, warp = tid >> 5;
    const int g = lane >> 2, t = lane & 3;
    const int qd = lane >> 3, rr = lane & 7;
    const int wm = warp >> 2, wn = warp & 3;

    if (tid < 128) red[tid] = 0.f;

#pragma unroll
    for (int j = 0; j < 8; j++) {
        const int id = j * 512 + tid;
        const int p = id >> 10, r = (id >> 3) & 127, ch = id & 7;
        const __nv_bfloat16* src =
            p == 0 ? Qhi + ((size_t)bh * 2048 + bm + r) * 64 + ch * 8 :
            p == 1 ? Qlo + ((size_t)bh * 2048 + bm + r) * 64 + ch * 8 :
            p == 2 ? Khi + ((size_t)bh * 2048 + bn + r) * 64 + ch * 8 :
                     Klo + ((size_t)bh * 2048 + bn + r) * 64 + ch * 8;
        cp16(dyn + p * 9216 + r * 72 + ch * 8, src);
    }
    CP_COMMIT(); CP_WAIT(0);
    __syncthreads();

    float acc[2][4][4] = {};
#pragma unroll
    for (int kc = 0; kc < 64; kc += 16) {
        uint32_t af[2][2][4];
#pragma unroll
        for (int mt = 0; mt < 2; mt++)
#pragma unroll
            for (int hl = 0; hl < 2; hl++)
                ldsm4(af[mt][hl],
                      s2u(dyn + hl * 9216 +
                          (wm * 32 + mt * 16 + (qd & 1) * 8 + rr) * 72 +
                          kc + (qd >> 1) * 8));

        uint32_t bfr[4][2][2];
#pragma unroll
        for (int np = 0; np < 2; np++)
#pragma unroll
            for (int hl = 0; hl < 2; hl++) {
                uint32_t bt[4];
                ldsm4(bt, s2u(dyn + 18432 + hl * 9216 +
                              (wn * 32 + np * 16 + (qd >> 1) * 8 + rr) * 72 +
                              kc + (qd & 1) * 8));
                bfr[np * 2][hl][0]     = bt[0];
                bfr[np * 2][hl][1]     = bt[1];
                bfr[np * 2 + 1][hl][0] = bt[2];
                bfr[np * 2 + 1][hl][1] = bt[3];
            }
#pragma unroll
        for (int mt = 0; mt < 2; mt++)
#pragma unroll
            for (int nt = 0; nt < 4; nt++) {
                mma_bf16(acc[mt][nt], af[mt][0], bfr[nt][0]);
                mma_bf16(acc[mt][nt], af[mt][0], bfr[nt][1]);
                mma_bf16(acc[mt][nt], af[mt][1], bfr[nt][0]);
            }
    }

    float rs[2][2] = {};
#pragma unroll
    for (int mt = 0; mt < 2; mt++) {
        const int rl0 = wm * 32 + mt * 16 + g;
#pragma unroll
        for (int nt = 0; nt < 4; nt++) {
            const int cl = wn * 32 + nt * 8 + 2 * t;
            const int gc = bn + cl;
            const float mk0 = mask[(size_t)b * 2048 + gc] * -1e9f;
            const float mk1 = mask[(size_t)b * 2048 + gc + 1] * -1e9f;
            const float e00 = __expf(acc[mt][nt][0] * 0.125f + mk0);
            const float e01 = __expf(acc[mt][nt][1] * 0.125f + mk1);
            const float e10 = __expf(acc[mt][nt][2] * 0.125f + mk0);
            const float e11 = __expf(acc[mt][nt][3] * 0.125f + mk1);
            __stcs((__half2*)(E + ((size_t)bh * 2048 + bm + rl0) * 2048 + gc),
                   __floats2half2_rn(e00, e01));
            __stcs((__half2*)(E + ((size_t)bh * 2048 + bm + rl0 + 8) * 2048 + gc),
                   __floats2half2_rn(e10, e11));
            rs[mt][0] += e00 + e01;
            rs[mt][1] += e10 + e11;
        }
    }
#pragma unroll
    for (int mt = 0; mt < 2; mt++)
#pragma unroll
        for (int hf = 0; hf < 2; hf++) {
            float v = rs[mt][hf];
            v += __shfl_xor_sync(0xffffffffu, v, 1);
            v += __shfl_xor_sync(0xffffffffu, v, 2);
            if (t == 0) atomicAdd(&red[wm * 32 + mt * 16 + hf * 8 + g], v);
        }
    __syncthreads();
    if (tid < 128) atomicAdd(&rowsum[(size_t)bh * 2048 + bm + tid], red[tid]);
}

// ---------------------------------------------------------------------------
// ctx_k: A = E (fp16, direct MMA operand), B = V fp16 hi/lo.
// ctx = diag(1/rowsum) * (E @ V): normalization folded into the epilogue.
// Normalized fp32 attn written from the same registers. 256 thr, 128x64 tile.
// ---------------------------------------------------------------------------
__global__ void __launch_bounds__(256, 2)
ctx_k(const __half* __restrict__ E,
      const __half* __restrict__ Vhi, const __half* __restrict__ Vlo,
      const float* __restrict__ rowsum, float* __restrict__ attn,
      float* __restrict__ ctx)
{
    __shared__ __align__(16) __half As[2][128][24];
    __shared__ __align__(16) __half Vs[2][2][16][72];

    const int bh = blockIdx.z, b = bh >> 4, h = bh & 15;
    const int bm = blockIdx.x * 128;
    const int tid = threadIdx.x, lane = tid & 31, warp = tid >> 5;
    const int g = lane >> 2, t = lane & 3;
    const int qd = lane >> 3, rr = lane & 7;
    const int wm = warp >> 1, wn = warp & 1;

    const int lr = tid >> 1, lc = tid & 1;   // row 0..127, 8-col chunk 0..1
    const float inv = 1.f / rowsum[(size_t)bh * 2048 + bm + lr];
    const __half* Erow = E + ((size_t)bh * 2048 + bm + lr) * 2048 + lc * 8;
    float* Arow = attn + ((size_t)bh * 2048 + bm + lr) * 2048 + lc * 8;

    const int vp = tid >> 7, vid = tid & 127, vkr = vid >> 3, vch = vid & 7;
    const __half* Vsrc = vp ? Vlo : Vhi;

    uint4 ev = __ldcs((const uint4*)Erow);
    cp16(&Vs[0][vp][vkr][vch * 8], Vsrc + ((size_t)bh * 2048 + vkr) * 64 + vch * 8);
    CP_COMMIT();

    float acc[2][4][4] = {};

    for (int it = 0; it < 128; ++it) {
        const int s = it & 1;
        // raw E tile into smem (no conversion needed — MMA consumes fp16)
        *(uint4*)&As[s][lr][lc * 8] = ev;
        // normalized attn write from the same registers
        {
            const __half2* h2 = (const __half2*)&ev;
            float p[8];
#pragma unroll
            for (int q = 0; q < 4; q++) {
                float2 f = __half22float2(h2[q]);
                p[2 * q]     = f.x * inv;
                p[2 * q + 1] = f.y * inv;
            }
            __stcs((float4*)(Arow + it * 16),     make_float4(p[0], p[1], p[2], p[3]));
            __stcs((float4*)(Arow + it * 16 + 4), make_float4(p[4], p[5], p[6], p[7]));
        }
        if (it + 1 < 128)
            ev = __ldcs((const uint4*)(Erow + (it + 1) * 16));
        CP_WAIT(0);
        __syncthreads();
        if (it + 1 < 128) {
            const int k0 = (it + 1) * 16;
            cp16(&Vs[s ^ 1][vp][vkr][vch * 8],
                 Vsrc + ((size_t)bh * 2048 + k0 + vkr) * 64 + vch * 8);
            CP_COMMIT();
        }

        uint32_t af[2][4];
#pragma unroll
        for (int mt = 0; mt < 2; mt++)
            ldsm4(af[mt],
                  s2u(&As[s][wm * 32 + mt * 16 + (qd & 1) * 8 + rr][(qd >> 1) * 8]));

        uint32_t bfr[4][2][2];
#pragma unroll
        for (int np = 0; np < 2; np++)
#pragma unroll
            for (int hl = 0; hl < 2; hl++) {
                uint32_t bt[4];
                ldsm4t(bt, s2u(&Vs[s][hl][(qd & 1) * 8 + rr]
                                        [wn * 32 + np * 16 + (qd >> 1) * 8]));
                bfr[np * 2][hl][0]     = bt[0];
                bfr[np * 2][hl][1]     = bt[1];
                bfr[np * 2 + 1][hl][0] = bt[2];
                bfr[np * 2 + 1][hl][1] = bt[3];
            }
#pragma unroll
        for (int mt = 0; mt < 2; mt++)
#pragma unroll
            for (int nt = 0; nt < 4; nt++) {
                mma_f16(acc[mt][nt], af[mt], bfr[nt][0]);
                mma_f16(acc[mt][nt], af[mt], bfr[nt][1]);
            }
    }

#pragma unroll
    for (int mt = 0; mt < 2; mt++) {
        const int row0 = bm + wm * 32 + mt * 16 + g;
        const float i0 = 1.f / rowsum[(size_t)bh * 2048 + row0];
        const float i1 = 1.f / rowsum[(size_t)bh * 2048 + row0 + 8];
#pragma unroll
        for (int nt = 0; nt < 4; nt++) {
            const int col = wn * 32 + nt * 8 + 2 * t;
            *(float2*)(ctx + ((size_t)b * 2048 + row0) * 1024 + h * 64 + col) =
                make_float2(acc[mt][nt][0] * i0, acc[mt][nt][1] * i0);
            *(float2*)(ctx + ((size_t)b * 2048 + row0 + 8) * 1024 + h * 64 + col) =
                make_float2(acc[mt][nt][2] * i1, acc[mt][nt][3] * i1);
        }
    }
}

// ---------------------------------------------------------------------------
extern "C" void kernel_launch(void* const* d_in, const int* in_sizes, int n_in,
                              void* d_out, int out_size)
{
    const float* q    = (const float*)d_in[0];
    const float* k    = (const float*)d_in[1];
    const float* v    = (const float*)d_in[2];
    const float* mask = (const float*)d_in[3];
    const float* Wq   = (const float*)d_in[4];
    const float* bq   = (const float*)d_in[5];
    const float* Wk   = (const float*)d_in[6];
    const float* bk   = (const float*)d_in[7];
    const float* Wv   = (const float*)d_in[8];
    const float* bv   = (const float*)d_in[9];
    const float* Wo   = (const float*)d_in[10];
    const float* bo   = (const float*)d_in[11];

    float* out  = (float*)d_out;
    float* attn = out + (size_t)BSz * Dd;

    __nv_bfloat16 *Qhi, *Qlo, *Khi, *Klo, *Vhi, *Vlo;
    float *ctxp, *rowsum;
    __half* E;
    cudaGetSymbolAddress((void**)&Qhi, g_Qhi);
    cudaGetSymbolAddress((void**)&Qlo, g_Qlo);
    cudaGetSymbolAddress((void**)&Khi, g_Khi);
    cudaGetSymbolAddress((void**)&Klo, g_Klo);
    cudaGetSymbolAddress((void**)&Vhi, g_Vhi);
    cudaGetSymbolAddress((void**)&Vlo, g_Vlo);
    cudaGetSymbolAddress((void**)&ctxp, g_ctx);
    cudaGetSymbolAddress((void**)&rowsum, g_rowsum);
    cudaGetSymbolAddress((void**)&E, g_e);

    cudaFuncSetAttribute(logits_k, cudaFuncAttributeMaxDynamicSharedMemorySize, 73728);

    zero_k<<<512, 256>>>(rowsum, BH * Ss);

    proj_k<0><<<dim3(8, 64, 3), 512>>>(q, k, v, Wq, Wk, Wv, bq, bk, bv,
                                       Qhi, Qlo, Khi, Klo, Vhi, Vlo, nullptr);

    logits_k<<<dim3(16, 16, 64), 512, 73728>>>(Qhi, Qlo, Khi, Klo, mask, E, rowsum);

    ctx_k<<<dim3(16, 1, 64), 256>>>(E, (const __half*)Vhi, (const __half*)Vlo,
                                    rowsum, attn, ctxp);

    proj_k<1><<<dim3(8, 64, 1), 512>>>(ctxp, ctxp, ctxp, Wo, Wo, Wo, bo, bo, bo,
                                       nullptr, nullptr, nullptr, nullptr,
                                       nullptr, nullptr, out);
}

// round 8
// speedup vs baseline: 1.2459x; 1.0766x over previous
#include <cuda_runtime.h>
#include <cuda_bf16.h>
#include <cuda_fp16.h>
#include <cstdint>

#define Ss  2048
#define Dd  1024
#define Hh  16
#define BH  64
#define BSz 8192

// Scratch (__device__ globals; no allocation)
__device__ __nv_bfloat16 g_Qhi[(size_t)BH * Ss * 64];
__device__ __nv_bfloat16 g_Qlo[(size_t)BH * Ss * 64];
__device__ __nv_bfloat16 g_Khi[(size_t)BH * Ss * 64];
__device__ __nv_bfloat16 g_Klo[(size_t)BH * Ss * 64];
__device__ __nv_bfloat16 g_Vhi[(size_t)BH * Ss * 64];   // holds fp16 bits for V
__device__ __nv_bfloat16 g_Vlo[(size_t)BH * Ss * 64];   // holds fp16 bits for V
__device__ float g_ctx[(size_t)BSz * Dd];
__device__ float g_rowsum[(size_t)BH * Ss];
__device__ __half g_e[(size_t)BH * Ss * Ss];   // unnormalized exp(logits), fp16

// ---------------------------------------------------------------------------
__device__ __forceinline__ uint32_t s2u(const void* p) {
    uint32_t a;
    asm("{ .reg .u64 t; cvta.to.shared.u64 t, %1; cvt.u32.u64 %0, t; }"
        : "=r"(a) : "l"(p));
    return a;
}
__device__ __forceinline__ void cp16(void* dst, const void* src) {
    asm volatile("cp.async.cg.shared.global [%0], [%1], 16;"
                 :: "r"(s2u(dst)), "l"(src));
}
#define CP_COMMIT() asm volatile("cp.async.commit_group;")
#define CP_WAIT(n)  asm volatile("cp.async.wait_group %0;" :: "n"(n))

__device__ __forceinline__ void ldsm4(uint32_t r[4], uint32_t a) {
    asm volatile("ldmatrix.sync.aligned.m8n8.x4.shared.b16 {%0,%1,%2,%3}, [%4];"
                 : "=r"(r[0]), "=r"(r[1]), "=r"(r[2]), "=r"(r[3]) : "r"(a));
}
__device__ __forceinline__ void ldsm4t(uint32_t r[4], uint32_t a) {
    asm volatile("ldmatrix.sync.aligned.m8n8.x4.trans.shared.b16 {%0,%1,%2,%3}, [%4];"
                 : "=r"(r[0]), "=r"(r[1]), "=r"(r[2]), "=r"(r[3]) : "r"(a));
}

__device__ __forceinline__ uint32_t pack_bf2(__nv_bfloat16 a, __nv_bfloat16 b) {
    return (uint32_t)__bfloat16_as_ushort(a) | ((uint32_t)__bfloat16_as_ushort(b) << 16);
}
__device__ __forceinline__ uint32_t pack_hf2(__half a, __half b) {
    return (uint32_t)__half_as_ushort(a) | ((uint32_t)__half_as_ushort(b) << 16);
}
__device__ __forceinline__ void split1(float x, __nv_bfloat16& h, __nv_bfloat16& l) {
    h = __float2bfloat16(x);
    l = __float2bfloat16(x - __bfloat162float(h));
}
__device__ __forceinline__ void splith(float x, __half& h, __half& l) {
    h = __float2half_rn(x);
    l = __float2half_rn(x - __half2float(h));
}
__device__ __forceinline__ void mma_bf16(float c[4], const uint32_t a[4], const uint32_t b[2]) {
    asm volatile(
        "mma.sync.aligned.m16n8k16.row.col.f32.bf16.bf16.f32 "
        "{%0,%1,%2,%3}, {%4,%5,%6,%7}, {%8,%9}, {%0,%1,%2,%3};"
        : "+f"(c[0]), "+f"(c[1]), "+f"(c[2]), "+f"(c[3])
        : "r"(a[0]), "r"(a[1]), "r"(a[2]), "r"(a[3]), "r"(b[0]), "r"(b[1]));
}
__device__ __forceinline__ void mma_f16(float c[4], const uint32_t a[4], const uint32_t b[2]) {
    asm volatile(
        "mma.sync.aligned.m16n8k16.row.col.f32.f16.f16.f32 "
        "{%0,%1,%2,%3}, {%4,%5,%6,%7}, {%8,%9}, {%0,%1,%2,%3};"
        : "+f"(c[0]), "+f"(c[1]), "+f"(c[2]), "+f"(c[3])
        : "r"(a[0]), "r"(a[1]), "r"(a[2]), "r"(a[3]), "r"(b[0]), "r"(b[1]));
}

__global__ void zero_k(float* p, int n) {
    int i = blockIdx.x * 256 + threadIdx.x;
    if (i < n) p[i] = 0.f;
}

// ---------------------------------------------------------------------------
// proj_k: Y = X[8192,1024] @ W[1024,1024] + bias.  z selects matrix set.
// z==2 (V) writes fp16 hi/lo (for fp16 MMA in ctx); z==0,1 write bf16 hi/lo.
// ---------------------------------------------------------------------------
template <int DENSE>
__global__ void __launch_bounds__(512, 1)
proj_k(const float* __restrict__ X0, const float* __restrict__ X1,
       const float* __restrict__ X2,
       const float* __restrict__ W0, const float* __restrict__ W1,
       const float* __restrict__ W2,
       const float* __restrict__ B0, const float* __restrict__ B1,
       const float* __restrict__ B2,
       __nv_bfloat16* __restrict__ H0, __nv_bfloat16* __restrict__ L0,
       __nv_bfloat16* __restrict__ H1, __nv_bfloat16* __restrict__ L1,
       __nv_bfloat16* __restrict__ H2, __nv_bfloat16* __restrict__ L2,
       float* __restrict__ OUT)
{
    const int z = blockIdx.z;
    const float* X  = z == 0 ? X0 : z == 1 ? X1 : X2;
    const float* W  = z == 0 ? W0 : z == 1 ? W1 : W2;
    const float* Bi = z == 0 ? B0 : z == 1 ? B1 : B2;
    __nv_bfloat16* Hd = z == 0 ? H0 : z == 1 ? H1 : H2;
    __nv_bfloat16* Ld = z == 0 ? L0 : z == 1 ? L1 : L2;

    __shared__ __align__(16) __nv_bfloat16 As[2][2][128][24];
    __shared__ __align__(16) __nv_bfloat16 Bs[2][2][16][136];

    const int tid = threadIdx.x, lane = tid & 31, warp = tid >> 5;
    const int g = lane >> 2, t = lane & 3;
    const int qd = lane >> 3, rr = lane & 7;
    const int wm = warp >> 2, wn = warp & 3;
    const int bm = blockIdx.y * 128, bn = blockIdx.x * 128;

    const int ar = tid >> 2, ac = tid & 3;
    const int br = tid >> 5, bc = (tid & 31) * 4;

    float acc[2][4][4] = {};

    float4 ax = *(const float4*)(X + (size_t)(bm + ar) * 1024 + ac * 4);
    float4 bx = *(const float4*)(W + (size_t)br * 1024 + bn + bc);

    for (int it = 0; it < 64; ++it) {
        const int s = it & 1;
        {
            __nv_bfloat16 h0, h1, h2, h3, l0, l1, l2, l3;
            split1(ax.x, h0, l0); split1(ax.y, h1, l1);
            split1(ax.z, h2, l2); split1(ax.w, h3, l3);
            *(uint2*)&As[s][0][ar][ac * 4] = make_uint2(pack_bf2(h0, h1), pack_bf2(h2, h3));
            *(uint2*)&As[s][1][ar][ac * 4] = make_uint2(pack_bf2(l0, l1), pack_bf2(l2, l3));
            split1(bx.x, h0, l0); split1(bx.y, h1, l1);
            split1(bx.z, h2, l2); split1(bx.w, h3, l3);
            *(uint2*)&Bs[s][0][br][bc] = make_uint2(pack_bf2(h0, h1), pack_bf2(h2, h3));
            *(uint2*)&Bs[s][1][br][bc] = make_uint2(pack_bf2(l0, l1), pack_bf2(l2, l3));
        }
        if (it + 1 < 64) {
            const int k0 = (it + 1) * 16;
            ax = *(const float4*)(X + (size_t)(bm + ar) * 1024 + k0 + ac * 4);
            bx = *(const float4*)(W + (size_t)(k0 + br) * 1024 + bn + bc);
        }
        __syncthreads();

        uint32_t af[2][2][4];
#pragma unroll
        for (int mt = 0; mt < 2; mt++)
#pragma unroll
            for (int hl = 0; hl < 2; hl++)
                ldsm4(af[mt][hl],
                      s2u(&As[s][hl][wm * 32 + mt * 16 + (qd & 1) * 8 + rr][(qd >> 1) * 8]));

        uint32_t bfr[4][2][2];
#pragma unroll
        for (int np = 0; np < 2; np++)
#pragma unroll
            for (int hl = 0; hl < 2; hl++) {
                uint32_t bt[4];
                ldsm4t(bt, s2u(&Bs[s][hl][(qd & 1) * 8 + rr]
                                        [wn * 32 + np * 16 + (qd >> 1) * 8]));
                bfr[np * 2][hl][0]     = bt[0];
                bfr[np * 2][hl][1]     = bt[1];
                bfr[np * 2 + 1][hl][0] = bt[2];
                bfr[np * 2 + 1][hl][1] = bt[3];
            }
#pragma unroll
        for (int mt = 0; mt < 2; mt++)
#pragma unroll
            for (int nt = 0; nt < 4; nt++) {
                mma_bf16(acc[mt][nt], af[mt][0], bfr[nt][0]);
                mma_bf16(acc[mt][nt], af[mt][0], bfr[nt][1]);
                mma_bf16(acc[mt][nt], af[mt][1], bfr[nt][0]);
            }
    }

#pragma unroll
    for (int mt = 0; mt < 2; mt++) {
        const int row0 = bm + wm * 32 + mt * 16 + g;
#pragma unroll
        for (int nt = 0; nt < 4; nt++) {
            const int col = bn + wn * 32 + nt * 8 + 2 * t;
            const float b0 = Bi[col], b1 = Bi[col + 1];
            const float v00 = acc[mt][nt][0] + b0, v01 = acc[mt][nt][1] + b1;
            const float v10 = acc[mt][nt][2] + b0, v11 = acc[mt][nt][3] + b1;
            if (DENSE) {
                *(float2*)(OUT + (size_t)row0 * 1024 + col)       = make_float2(v00, v01);
                *(float2*)(OUT + (size_t)(row0 + 8) * 1024 + col) = make_float2(v10, v11);
            } else {
                const int hh = col >> 6, dc = col & 63;
                const int b_ = row0 >> 11;
                const size_t o0 = (((size_t)b_ * 16 + hh) * 2048 + (row0 & 2047)) * 64 + dc;
                const size_t o1 = (((size_t)b_ * 16 + hh) * 2048 + ((row0 + 8) & 2047)) * 64 + dc;
                if (z == 2) {   // V: fp16 hi/lo for fp16 MMA in ctx_k
                    __half h0, l0, h1, l1;
                    splith(v00, h0, l0); splith(v01, h1, l1);
                    *(uint32_t*)&Hd[o0] = pack_hf2(h0, h1);
                    *(uint32_t*)&Ld[o0] = pack_hf2(l0, l1);
                    splith(v10, h0, l0); splith(v11, h1, l1);
                    *(uint32_t*)&Hd[o1] = pack_hf2(h0, h1);
                    *(uint32_t*)&Ld[o1] = pack_hf2(l0, l1);
                } else {        // Q/K: bf16 hi/lo for split-bf16 MMA in logits_k
                    __nv_bfloat16 h0, l0, h1, l1;
                    split1(v00, h0, l0); split1(v01, h1, l1);
                    *(uint32_t*)&Hd[o0] = pack_bf2(h0, h1);
                    *(uint32_t*)&Ld[o0] = pack_bf2(l0, l1);
                    split1(v10, h0, l0); split1(v11, h1, l1);
                    *(uint32_t*)&Hd[o1] = pack_bf2(h0, h1);
                    *(uint32_t*)&Ld[o1] = pack_bf2(l0, l1);
                }
            }
        }
    }
}

// ---------------------------------------------------------------------------
// logits_k: e = exp(0.125*QK^T + mask*-1e9) stored FP16; rowsum += partials.
// ---------------------------------------------------------------------------
__global__ void __launch_bounds__(512, 1)
logits_k(const __nv_bfloat16* __restrict__ Qhi, const __nv_bfloat16* __restrict__ Qlo,
         const __nv_bfloat16* __restrict__ Khi, const __nv_bfloat16* __restrict__ Klo,
         const float* __restrict__ mask, __half* __restrict__ E,
         float* __restrict__ rowsum)
{
    extern __shared__ __nv_bfloat16 dyn[];
    __shared__ float red[128];

    const int bh = blockIdx.z, b = bh >> 4;
    const int bm = blockIdx.y * 128, bn = blockIdx.x * 128;
    const int tid = threadIdx.x, lane = tid & 31, warp = tid >> 5;
    const int g = lane >> 2, t = lane & 3;
    const int qd = lane >> 3, rr = lane & 7;
    const int wm = warp >> 2, wn = warp & 3;

    if (tid < 128) red[tid] = 0.f;

#pragma unroll
    for (int j = 0; j < 8; j++) {
        const int id = j * 512 + tid;
        const int p = id >> 10, r = (id >> 3) & 127, ch = id & 7;
        const __nv_bfloat16* src =
            p == 0 ? Qhi + ((size_t)bh * 2048 + bm + r) * 64 + ch * 8 :
            p == 1 ? Qlo + ((size_t)bh * 2048 + bm + r) * 64 + ch * 8 :
            p == 2 ? Khi + ((size_t)bh * 2048 + bn + r) * 64 + ch * 8 :
                     Klo + ((size_t)bh * 2048 + bn + r) * 64 + ch * 8;
        cp16(dyn + p * 9216 + r * 72 + ch * 8, src);
    }
    CP_COMMIT(); CP_WAIT(0);
    __syncthreads();

    float acc[2][4][4] = {};
#pragma unroll
    for (int kc = 0; kc < 64; kc += 16) {
        uint32_t af[2][2][4];
#pragma unroll
        for (int mt = 0; mt < 2; mt++)
#pragma unroll
            for (int hl = 0; hl < 2; hl++)
                ldsm4(af[mt][hl],
                      s2u(dyn + hl * 9216 +
                          (wm * 32 + mt * 16 + (qd & 1) * 8 + rr) * 72 +
                          kc + (qd >> 1) * 8));

        uint32_t bfr[4][2][2];
#pragma unroll
        for (int np = 0; np < 2; np++)
#pragma unroll
            for (int hl = 0; hl < 2; hl++) {
                uint32_t bt[4];
                ldsm4(bt, s2u(dyn + 18432 + hl * 9216 +
                              (wn * 32 + np * 16 + (qd >> 1) * 8 + rr) * 72 +
                              kc + (qd & 1) * 8));
                bfr[np * 2][hl][0]     = bt[0];
                bfr[np * 2][hl][1]     = bt[1];
                bfr[np * 2 + 1][hl][0] = bt[2];
                bfr[np * 2 + 1][hl][1] = bt[3];
            }
#pragma unroll
        for (int mt = 0; mt < 2; mt++)
#pragma unroll
            for (int nt = 0; nt < 4; nt++) {
                mma_bf16(acc[mt][nt], af[mt][0], bfr[nt][0]);
                mma_bf16(acc[mt][nt], af[mt][0], bfr[nt][1]);
                mma_bf16(acc[mt][nt], af[mt][1], bfr[nt][0]);
            }
    }

    float rs[2][2] = {};
#pragma unroll
    for (int mt = 0; mt < 2; mt++) {
        const int rl0 = wm * 32 + mt * 16 + g;
#pragma unroll
        for (int nt = 0; nt < 4; nt++) {
            const int cl = wn * 32 + nt * 8 + 2 * t;
            const int gc = bn + cl;
            const float mk0 = mask[(size_t)b * 2048 + gc] * -1e9f;
            const float mk1 = mask[(size_t)b * 2048 + gc + 1] * -1e9f;
            const float e00 = __expf(acc[mt][nt][0] * 0.125f + mk0);
            const float e01 = __expf(acc[mt][nt][1] * 0.125f + mk1);
            const float e10 = __expf(acc[mt][nt][2] * 0.125f + mk0);
            const float e11 = __expf(acc[mt][nt][3] * 0.125f + mk1);
            __stcs((__half2*)(E + ((size_t)bh * 2048 + bm + rl0) * 2048 + gc),
                   __floats2half2_rn(e00, e01));
            __stcs((__half2*)(E + ((size_t)bh * 2048 + bm + rl0 + 8) * 2048 + gc),
                   __floats2half2_rn(e10, e11));
            rs[mt][0] += e00 + e01;
            rs[mt][1] += e10 + e11;
        }
    }
#pragma unroll
    for (int mt = 0; mt < 2; mt++)
#pragma unroll
        for (int hf = 0; hf < 2; hf++) {
            float v = rs[mt][hf];
            v += __shfl_xor_sync(0xffffffffu, v, 1);
            v += __shfl_xor_sync(0xffffffffu, v, 2);
            if (t == 0) atomicAdd(&red[wm * 32 + mt * 16 + hf * 8 + g], v);
        }
    __syncthreads();
    if (tid < 128) atomicAdd(&rowsum[(size_t)bh * 2048 + bm + tid], red[tid]);
}

// ---------------------------------------------------------------------------
// ctx_k: E and V both streamed via 4-stage cp.async ring (3 in flight).
// A = E (fp16, raw MMA operand); normalization in epilogue; normalized fp32
// attn written from smem after each stage barrier. 256 thr, 128x64 tile.
// ---------------------------------------------------------------------------
__global__ void __launch_bounds__(256, 2)
ctx_k(const __half* __restrict__ E,
      const __half* __restrict__ Vhi, const __half* __restrict__ Vlo,
      const float* __restrict__ rowsum, float* __restrict__ attn,
      float* __restrict__ ctx)
{
    __shared__ __align__(16) __half As[4][128][24];
    __shared__ __align__(16) __half Vs[4][2][16][72];

    const int bh = blockIdx.z, b = bh >> 4, h = bh & 15;
    const int bm = blockIdx.x * 128;
    const int tid = threadIdx.x, lane = tid & 31, warp = tid >> 5;
    const int g = lane >> 2, t = lane & 3;
    const int qd = lane >> 3, rr = lane & 7;
    const int wm = warp >> 1, wn = warp & 1;

    // loaders: E — thread owns (row lr, 8-col chunk lc); V — as before
    const int lr = tid >> 1, lc = tid & 1;
    const __half* Ebase = E + ((size_t)bh * 2048 + bm + lr) * 2048 + lc * 8;
    const int vp = tid >> 7, vid = tid & 127, vkr = vid >> 3, vch = vid & 7;
    const __half* Vbase = (vp ? Vlo : Vhi) + ((size_t)bh * 2048 + vkr) * 64 + vch * 8;

    const float inv = 1.f / rowsum[(size_t)bh * 2048 + bm + lr];
    float* Arow = attn + ((size_t)bh * 2048 + bm + lr) * 2048 + lc * 8;

#define LOAD_STAGE(st, it_) do {                                   \
        cp16(&As[st][lr][lc * 8], Ebase + (size_t)(it_) * 16);     \
        cp16(&Vs[st][vp][vkr][vch * 8], Vbase + (size_t)(it_) * 1024); \
        CP_COMMIT();                                               \
    } while (0)

    LOAD_STAGE(0, 0);
    LOAD_STAGE(1, 1);
    LOAD_STAGE(2, 2);

    float acc[2][4][4] = {};

    for (int it = 0; it < 128; ++it) {
        const int st = it & 3;
        if (it + 3 < 128) { CP_WAIT(2); } else { CP_WAIT(0); }
        __syncthreads();
        if (it + 3 < 128) LOAD_STAGE((it + 3) & 3, it + 3);

        // normalized fp32 attn write from smem
        {
            const uint4 ev = *(const uint4*)&As[st][lr][lc * 8];
            const __half2* h2 = (const __half2*)&ev;
            float p[8];
#pragma unroll
            for (int q = 0; q < 4; q++) {
                float2 f = __half22float2(h2[q]);
                p[2 * q]     = f.x * inv;
                p[2 * q + 1] = f.y * inv;
            }
            __stcs((float4*)(Arow + it * 16),     make_float4(p[0], p[1], p[2], p[3]));
            __stcs((float4*)(Arow + it * 16 + 4), make_float4(p[4], p[5], p[6], p[7]));
        }

        uint32_t af[2][4];
#pragma unroll
        for (int mt = 0; mt < 2; mt++)
            ldsm4(af[mt],
                  s2u(&As[st][wm * 32 + mt * 16 + (qd & 1) * 8 + rr][(qd >> 1) * 8]));

        uint32_t bfr[4][2][2];
#pragma unroll
        for (int np = 0; np < 2; np++)
#pragma unroll
            for (int hl = 0; hl < 2; hl++) {
                uint32_t bt[4];
                ldsm4t(bt, s2u(&Vs[st][hl][(qd & 1) * 8 + rr]
                                         [wn * 32 + np * 16 + (qd >> 1) * 8]));
                bfr[np * 2][hl][0]     = bt[0];
                bfr[np * 2][hl][1]     = bt[1];
                bfr[np * 2 + 1][hl][0] = bt[2];
                bfr[np * 2 + 1][hl][1] = bt[3];
            }
#pragma unroll
        for (int mt = 0; mt < 2; mt++)
#pragma unroll
            for (int nt = 0; nt < 4; nt++) {
                mma_f16(acc[mt][nt], af[mt], bfr[nt][0]);
                mma_f16(acc[mt][nt], af[mt], bfr[nt][1]);
            }
    }
#undef LOAD_STAGE

#pragma unroll
    for (int mt = 0; mt < 2; mt++) {
        const int row0 = bm + wm * 32 + mt * 16 + g;
        const float i0 = 1.f / rowsum[(size_t)bh * 2048 + row0];
        const float i1 = 1.f / rowsum[(size_t)bh * 2048 + row0 + 8];
#pragma unroll
        for (int nt = 0; nt < 4; nt++) {
            const int col = wn * 32 + nt * 8 + 2 * t;
            *(float2*)(ctx + ((size_t)b * 2048 + row0) * 1024 + h * 64 + col) =
                make_float2(acc[mt][nt][0] * i0, acc[mt][nt][1] * i0);
            *(float2*)(ctx + ((size_t)b * 2048 + row0 + 8) * 1024 + h * 64 + col) =
                make_float2(acc[mt][nt][2] * i1, acc[mt][nt][3] * i1);
        }
    }
}

// ---------------------------------------------------------------------------
extern "C" void kernel_launch(void* const* d_in, const int* in_sizes, int n_in,
                              void* d_out, int out_size)
{
    const float* q    = (const float*)d_in[0];
    const float* k    = (const float*)d_in[1];
    const float* v    = (const float*)d_in[2];
    const float* mask = (const float*)d_in[3];
    const float* Wq   = (const float*)d_in[4];
    const float* bq   = (const float*)d_in[5];
    const float* Wk   = (const float*)d_in[6];
    const float* bk   = (const float*)d_in[7];
    const float* Wv   = (const float*)d_in[8];
    const float* bv   = (const float*)d_in[9];
    const float* Wo   = (const float*)d_in[10];
    const float* bo   = (const float*)d_in[11];

    float* out  = (float*)d_out;
    float* attn = out + (size_t)BSz * Dd;

    __nv_bfloat16 *Qhi, *Qlo, *Khi, *Klo, *Vhi, *Vlo;
    float *ctxp, *rowsum;
    __half* E;
    cudaGetSymbolAddress((void**)&Qhi, g_Qhi);
    cudaGetSymbolAddress((void**)&Qlo, g_Qlo);
    cudaGetSymbolAddress((void**)&Khi, g_Khi);
    cudaGetSymbolAddress((void**)&Klo, g_Klo);
    cudaGetSymbolAddress((void**)&Vhi, g_Vhi);
    cudaGetSymbolAddress((void**)&Vlo, g_Vlo);
    cudaGetSymbolAddress((void**)&ctxp, g_ctx);
    cudaGetSymbolAddress((void**)&rowsum, g_rowsum);
    cudaGetSymbolAddress((void**)&E, g_e);

    cudaFuncSetAttribute(logits_k, cudaFuncAttributeMaxDynamicSharedMemorySize, 73728);

    zero_k<<<512, 256>>>(rowsum, BH * Ss);

    proj_k<0><<<dim3(8, 64, 3), 512>>>(q, k, v, Wq, Wk, Wv, bq, bk, bv,
                                       Qhi, Qlo, Khi, Klo, Vhi, Vlo, nullptr);

    logits_k<<<dim3(16, 16, 64), 512, 73728>>>(Qhi, Qlo, Khi, Klo, mask, E, rowsum);

    ctx_k<<<dim3(16, 1, 64), 256>>>(E, (const __half*)Vhi, (const __half*)Vlo,
                                    rowsum, attn, ctxp);

    proj_k<1><<<dim3(8, 64, 1), 512>>>(ctxp, ctxp, ctxp, Wo, Wo, Wo, bo, bo, bo,
                                       nullptr, nullptr, nullptr, nullptr,
                                       nullptr, nullptr, out);
}

// round 9
// speedup vs baseline: 1.2697x; 1.0191x over previous
#include <cuda_runtime.h>
#include <cuda_bf16.h>
#include <cuda_fp16.h>
#include <cstdint>

#define Ss  2048
#define Dd  1024
#define Hh  16
#define BH  64
#define BSz 8192

// Scratch (__device__ globals; no allocation)
__device__ __nv_bfloat16 g_Qhi[(size_t)BH * Ss * 64];
__device__ __nv_bfloat16 g_Qlo[(size_t)BH * Ss * 64];
__device__ __nv_bfloat16 g_Khi[(size_t)BH * Ss * 64];
__device__ __nv_bfloat16 g_Klo[(size_t)BH * Ss * 64];
__device__ __nv_bfloat16 g_Vhi[(size_t)BH * Ss * 64];   // holds fp16 bits for V
__device__ __nv_bfloat16 g_Vlo[(size_t)BH * Ss * 64];   // holds fp16 bits (unused by ctx now)
__device__ float g_ctx[(size_t)BSz * Dd];
__device__ float g_rowsum[(size_t)BH * Ss];
__device__ __half g_e[(size_t)BH * Ss * Ss];   // unnormalized exp(logits), fp16

// ---------------------------------------------------------------------------
__device__ __forceinline__ uint32_t s2u(const void* p) {
    uint32_t a;
    asm("{ .reg .u64 t; cvta.to.shared.u64 t, %1; cvt.u32.u64 %0, t; }"
        : "=r"(a) : "l"(p));
    return a;
}
__device__ __forceinline__ void cp16(void* dst, const void* src) {
    asm volatile("cp.async.cg.shared.global [%0], [%1], 16;"
                 :: "r"(s2u(dst)), "l"(src));
}
#define CP_COMMIT() asm volatile("cp.async.commit_group;")
#define CP_WAIT(n)  asm volatile("cp.async.wait_group %0;" :: "n"(n))

__device__ __forceinline__ void ldsm4(uint32_t r[4], uint32_t a) {
    asm volatile("ldmatrix.sync.aligned.m8n8.x4.shared.b16 {%0,%1,%2,%3}, [%4];"
                 : "=r"(r[0]), "=r"(r[1]), "=r"(r[2]), "=r"(r[3]) : "r"(a));
}
__device__ __forceinline__ void ldsm4t(uint32_t r[4], uint32_t a) {
    asm volatile("ldmatrix.sync.aligned.m8n8.x4.trans.shared.b16 {%0,%1,%2,%3}, [%4];"
                 : "=r"(r[0]), "=r"(r[1]), "=r"(r[2]), "=r"(r[3]) : "r"(a));
}

__device__ __forceinline__ uint32_t pack_bf2(__nv_bfloat16 a, __nv_bfloat16 b) {
    return (uint32_t)__bfloat16_as_ushort(a) | ((uint32_t)__bfloat16_as_ushort(b) << 16);
}
__device__ __forceinline__ uint32_t pack_hf2(__half a, __half b) {
    return (uint32_t)__half_as_ushort(a) | ((uint32_t)__half_as_ushort(b) << 16);
}
__device__ __forceinline__ void split1(float x, __nv_bfloat16& h, __nv_bfloat16& l) {
    h = __float2bfloat16(x);
    l = __float2bfloat16(x - __bfloat162float(h));
}
__device__ __forceinline__ void splith(float x, __half& h, __half& l) {
    h = __float2half_rn(x);
    l = __float2half_rn(x - __half2float(h));
}
__device__ __forceinline__ void mma_bf16(float c[4], const uint32_t a[4], const uint32_t b[2]) {
    asm volatile(
        "mma.sync.aligned.m16n8k16.row.col.f32.bf16.bf16.f32 "
        "{%0,%1,%2,%3}, {%4,%5,%6,%7}, {%8,%9}, {%0,%1,%2,%3};"
        : "+f"(c[0]), "+f"(c[1]), "+f"(c[2]), "+f"(c[3])
        : "r"(a[0]), "r"(a[1]), "r"(a[2]), "r"(a[3]), "r"(b[0]), "r"(b[1]));
}
__device__ __forceinline__ void mma_f16(float c[4], const uint32_t a[4], const uint32_t b[2]) {
    asm volatile(
        "mma.sync.aligned.m16n8k16.row.col.f32.f16.f16.f32 "
        "{%0,%1,%2,%3}, {%4,%5,%6,%7}, {%8,%9}, {%0,%1,%2,%3};"
        : "+f"(c[0]), "+f"(c[1]), "+f"(c[2]), "+f"(c[3])
        : "r"(a[0]), "r"(a[1]), "r"(a[2]), "r"(a[3]), "r"(b[0]), "r"(b[1]));
}

__global__ void zero_k(float* p, int n) {
    int i = blockIdx.x * 256 + threadIdx.x;
    if (i < n) p[i] = 0.f;
}

// ---------------------------------------------------------------------------
// proj_k: Y = X[8192,1024] @ W[1024,1024] + bias.  z selects matrix set.
// z==2 (V) writes fp16 hi/lo; z==0,1 write bf16 hi/lo.
// ---------------------------------------------------------------------------
template <int DENSE>
__global__ void __launch_bounds__(512, 1)
proj_k(const float* __restrict__ X0, const float* __restrict__ X1,
       const float* __restrict__ X2,
       const float* __restrict__ W0, const float* __restrict__ W1,
       const float* __restrict__ W2,
       const float* __restrict__ B0, const float* __restrict__ B1,
       const float* __restrict__ B2,
       __nv_bfloat16* __restrict__ H0, __nv_bfloat16* __restrict__ L0,
       __nv_bfloat16* __restrict__ H1, __nv_bfloat16* __restrict__ L1,
       __nv_bfloat16* __restrict__ H2, __nv_bfloat16* __restrict__ L2,
       float* __restrict__ OUT)
{
    const int z = blockIdx.z;
    const float* X  = z == 0 ? X0 : z == 1 ? X1 : X2;
    const float* W  = z == 0 ? W0 : z == 1 ? W1 : W2;
    const float* Bi = z == 0 ? B0 : z == 1 ? B1 : B2;
    __nv_bfloat16* Hd = z == 0 ? H0 : z == 1 ? H1 : H2;
    __nv_bfloat16* Ld = z == 0 ? L0 : z == 1 ? L1 : L2;

    __shared__ __align__(16) __nv_bfloat16 As[2][2][128][24];
    __shared__ __align__(16) __nv_bfloat16 Bs[2][2][16][136];

    const int tid = threadIdx.x, lane = tid & 31, warp = tid >> 5;
    const int g = lane >> 2, t = lane & 3;
    const int qd = lane >> 3, rr = lane & 7;
    const int wm = warp >> 2, wn = warp & 3;
    const int bm = blockIdx.y * 128, bn = blockIdx.x * 128;

    const int ar = tid >> 2, ac = tid & 3;
    const int br = tid >> 5, bc = (tid & 31) * 4;

    float acc[2][4][4] = {};

    float4 ax = *(const float4*)(X + (size_t)(bm + ar) * 1024 + ac * 4);
    float4 bx = *(const float4*)(W + (size_t)br * 1024 + bn + bc);

    for (int it = 0; it < 64; ++it) {
        const int s = it & 1;
        {
            __nv_bfloat16 h0, h1, h2, h3, l0, l1, l2, l3;
            split1(ax.x, h0, l0); split1(ax.y, h1, l1);
            split1(ax.z, h2, l2); split1(ax.w, h3, l3);
            *(uint2*)&As[s][0][ar][ac * 4] = make_uint2(pack_bf2(h0, h1), pack_bf2(h2, h3));
            *(uint2*)&As[s][1][ar][ac * 4] = make_uint2(pack_bf2(l0, l1), pack_bf2(l2, l3));
            split1(bx.x, h0, l0); split1(bx.y, h1, l1);
            split1(bx.z, h2, l2); split1(bx.w, h3, l3);
            *(uint2*)&Bs[s][0][br][bc] = make_uint2(pack_bf2(h0, h1), pack_bf2(h2, h3));
            *(uint2*)&Bs[s][1][br][bc] = make_uint2(pack_bf2(l0, l1), pack_bf2(l2, l3));
        }
        if (it + 1 < 64) {
            const int k0 = (it + 1) * 16;
            ax = *(const float4*)(X + (size_t)(bm + ar) * 1024 + k0 + ac * 4);
            bx = *(const float4*)(W + (size_t)(k0 + br) * 1024 + bn + bc);
        }
        __syncthreads();

        uint32_t af[2][2][4];
#pragma unroll
        for (int mt = 0; mt < 2; mt++)
#pragma unroll
            for (int hl = 0; hl < 2; hl++)
                ldsm4(af[mt][hl],
                      s2u(&As[s][hl][wm * 32 + mt * 16 + (qd & 1) * 8 + rr][(qd >> 1) * 8]));

        uint32_t bfr[4][2][2];
#pragma unroll
        for (int np = 0; np < 2; np++)
#pragma unroll
            for (int hl = 0; hl < 2; hl++) {
                uint32_t bt[4];
                ldsm4t(bt, s2u(&Bs[s][hl][(qd & 1) * 8 + rr]
                                        [wn * 32 + np * 16 + (qd >> 1) * 8]));
                bfr[np * 2][hl][0]     = bt[0];
                bfr[np * 2][hl][1]     = bt[1];
                bfr[np * 2 + 1][hl][0] = bt[2];
                bfr[np * 2 + 1][hl][1] = bt[3];
            }
#pragma unroll
        for (int mt = 0; mt < 2; mt++)
#pragma unroll
            for (int nt = 0; nt < 4; nt++) {
                mma_bf16(acc[mt][nt], af[mt][0], bfr[nt][0]);
                mma_bf16(acc[mt][nt], af[mt][0], bfr[nt][1]);
                mma_bf16(acc[mt][nt], af[mt][1], bfr[nt][0]);
            }
    }

#pragma unroll
    for (int mt = 0; mt < 2; mt++) {
        const int row0 = bm + wm * 32 + mt * 16 + g;
#pragma unroll
        for (int nt = 0; nt < 4; nt++) {
            const int col = bn + wn * 32 + nt * 8 + 2 * t;
            const float b0 = Bi[col], b1 = Bi[col + 1];
            const float v00 = acc[mt][nt][0] + b0, v01 = acc[mt][nt][1] + b1;
            const float v10 = acc[mt][nt][2] + b0, v11 = acc[mt][nt][3] + b1;
            if (DENSE) {
                *(float2*)(OUT + (size_t)row0 * 1024 + col)       = make_float2(v00, v01);
                *(float2*)(OUT + (size_t)(row0 + 8) * 1024 + col) = make_float2(v10, v11);
            } else {
                const int hh = col >> 6, dc = col & 63;
                const int b_ = row0 >> 11;
                const size_t o0 = (((size_t)b_ * 16 + hh) * 2048 + (row0 & 2047)) * 64 + dc;
                const size_t o1 = (((size_t)b_ * 16 + hh) * 2048 + ((row0 + 8) & 2047)) * 64 + dc;
                if (z == 2) {   // V: fp16 hi/lo (ctx uses hi)
                    __half h0, l0, h1, l1;
                    splith(v00, h0, l0); splith(v01, h1, l1);
                    *(uint32_t*)&Hd[o0] = pack_hf2(h0, h1);
                    *(uint32_t*)&Ld[o0] = pack_hf2(l0, l1);
                    splith(v10, h0, l0); splith(v11, h1, l1);
                    *(uint32_t*)&Hd[o1] = pack_hf2(h0, h1);
                    *(uint32_t*)&Ld[o1] = pack_hf2(l0, l1);
                } else {        // Q/K: bf16 hi/lo for split-bf16 MMA in logits_k
                    __nv_bfloat16 h0, l0, h1, l1;
                    split1(v00, h0, l0); split1(v01, h1, l1);
                    *(uint32_t*)&Hd[o0] = pack_bf2(h0, h1);
                    *(uint32_t*)&Ld[o0] = pack_bf2(l0, l1);
                    split1(v10, h0, l0); split1(v11, h1, l1);
                    *(uint32_t*)&Hd[o1] = pack_bf2(h0, h1);
                    *(uint32_t*)&Ld[o1] = pack_bf2(l0, l1);
                }
            }
        }
    }
}

// ---------------------------------------------------------------------------
// logits_k: e = exp(0.125*QK^T + mask*-1e9) stored FP16; rowsum += partials.
// ---------------------------------------------------------------------------
__global__ void __launch_bounds__(512, 1)
logits_k(const __nv_bfloat16* __restrict__ Qhi, const __nv_bfloat16* __restrict__ Qlo,
         const __nv_bfloat16* __restrict__ Khi, const __nv_bfloat16* __restrict__ Klo,
         const float* __restrict__ mask, __half* __restrict__ E,
         float* __restrict__ rowsum)
{
    extern __shared__ __nv_bfloat16 dyn[];
    __shared__ float red[128];

    const int bh = blockIdx.z, b = bh >> 4;
    const int bm = blockIdx.y * 128, bn = blockIdx.x * 128;
    const int tid = threadIdx.x, lane = tid & 31, warp = tid >> 5;
    const int g = lane >> 2, t = lane & 3;
    const int qd = lane >> 3, rr = lane & 7;
    const int wm = warp >> 2, wn = warp & 3;

    if (tid < 128) red[tid] = 0.f;

#pragma unroll
    for (int j = 0; j < 8; j++) {
        const int id = j * 512 + tid;
        const int p = id >> 10, r = (id >> 3) & 127, ch = id & 7;
        const __nv_bfloat16* src =
            p == 0 ? Qhi + ((size_t)bh * 2048 + bm + r) * 64 + ch * 8 :
            p == 1 ? Qlo + ((size_t)bh * 2048 + bm + r) * 64 + ch * 8 :
            p == 2 ? Khi + ((size_t)bh * 2048 + bn + r) * 64 + ch * 8 :
                     Klo + ((size_t)bh * 2048 + bn + r) * 64 + ch * 8;
        cp16(dyn + p * 9216 + r * 72 + ch * 8, src);
    }
    CP_COMMIT(); CP_WAIT(0);
    __syncthreads();

    float acc[2][4][4] = {};
#pragma unroll
    for (int kc = 0; kc < 64; kc += 16) {
        uint32_t af[2][2][4];
#pragma unroll
        for (int mt = 0; mt < 2; mt++)
#pragma unroll
            for (int hl = 0; hl < 2; hl++)
                ldsm4(af[mt][hl],
                      s2u(dyn + hl * 9216 +
                          (wm * 32 + mt * 16 + (qd & 1) * 8 + rr) * 72 +
                          kc + (qd >> 1) * 8));

        uint32_t bfr[4][2][2];
#pragma unroll
        for (int np = 0; np < 2; np++)
#pragma unroll
            for (int hl = 0; hl < 2; hl++) {
                uint32_t bt[4];
                ldsm4(bt, s2u(dyn + 18432 + hl * 9216 +
                              (wn * 32 + np * 16 + (qd >> 1) * 8 + rr) * 72 +
                              kc + (qd & 1) * 8));
                bfr[np * 2][hl][0]     = bt[0];
                bfr[np * 2][hl][1]     = bt[1];
                bfr[np * 2 + 1][hl][0] = bt[2];
                bfr[np * 2 + 1][hl][1] = bt[3];
            }
#pragma unroll
        for (int mt = 0; mt < 2; mt++)
#pragma unroll
            for (int nt = 0; nt < 4; nt++) {
                mma_bf16(acc[mt][nt], af[mt][0], bfr[nt][0]);
                mma_bf16(acc[mt][nt], af[mt][0], bfr[nt][1]);
                mma_bf16(acc[mt][nt], af[mt][1], bfr[nt][0]);
            }
    }

    float rs[2][2] = {};
#pragma unroll
    for (int mt = 0; mt < 2; mt++) {
        const int rl0 = wm * 32 + mt * 16 + g;
#pragma unroll
        for (int nt = 0; nt < 4; nt++) {
            const int cl = wn * 32 + nt * 8 + 2 * t;
            const int gc = bn + cl;
            const float mk0 = mask[(size_t)b * 2048 + gc] * -1e9f;
            const float mk1 = mask[(size_t)b * 2048 + gc + 1] * -1e9f;
            const float e00 = __expf(acc[mt][nt][0] * 0.125f + mk0);
            const float e01 = __expf(acc[mt][nt][1] * 0.125f + mk1);
            const float e10 = __expf(acc[mt][nt][2] * 0.125f + mk0);
            const float e11 = __expf(acc[mt][nt][3] * 0.125f + mk1);
            __stcs((__half2*)(E + ((size_t)bh * 2048 + bm + rl0) * 2048 + gc),
                   __floats2half2_rn(e00, e01));
            __stcs((__half2*)(E + ((size_t)bh * 2048 + bm + rl0 + 8) * 2048 + gc),
                   __floats2half2_rn(e10, e11));
            rs[mt][0] += e00 + e01;
            rs[mt][1] += e10 + e11;
        }
    }
#pragma unroll
    for (int mt = 0; mt < 2; mt++)
#pragma unroll
        for (int hf = 0; hf < 2; hf++) {
            float v = rs[mt][hf];
            v += __shfl_xor_sync(0xffffffffu, v, 1);
            v += __shfl_xor_sync(0xffffffffu, v, 2);
            if (t == 0) atomicAdd(&red[wm * 32 + mt * 16 + hf * 8 + g], v);
        }
    __syncthreads();
    if (tid < 128) atomicAdd(&rowsum[(size_t)bh * 2048 + bm + tid], red[tid]);
}

// ---------------------------------------------------------------------------
// ctx_k: E + V(hi fp16 only) streamed via 6-stage cp.async ring (5 in flight).
// 8 MMAs/iter. 256 thr, 128x64 tile, 3 CTAs/SM, dynamic smem.
// ---------------------------------------------------------------------------
#define CTX_SMEM (6 * 128 * 24 * 2 + 6 * 16 * 72 * 2)   // 50688 bytes

__global__ void __launch_bounds__(256, 3)
ctx_k(const __half* __restrict__ E, const __half* __restrict__ Vhi,
      const float* __restrict__ rowsum, float* __restrict__ attn,
      float* __restrict__ ctx)
{
    extern __shared__ __align__(16) __half smh[];
    __half (*As)[128][24] = (__half(*)[128][24])smh;
    __half (*Vs)[16][72]  = (__half(*)[16][72])(smh + 6 * 128 * 24);

    const int bh = blockIdx.z, b = bh >> 4, h = bh & 15;
    const int bm = blockIdx.x * 128;
    const int tid = threadIdx.x, lane = tid & 31, warp = tid >> 5;
    const int g = lane >> 2, t = lane & 3;
    const int qd = lane >> 3, rr = lane & 7;
    const int wm = warp >> 1, wn = warp & 1;

    // E loader: all 256 threads, (row lr, 8-col chunk lc)
    const int lr = tid >> 1, lc = tid & 1;
    const __half* Ebase = E + ((size_t)bh * 2048 + bm + lr) * 2048 + lc * 8;
    // V loader: threads 0..127, 16x64 fp16 per stage
    const int vkr = (tid & 127) >> 3, vch = tid & 7;
    const __half* Vbase = Vhi + ((size_t)bh * 2048 + vkr) * 64 + vch * 8;

    const float inv = 1.f / rowsum[(size_t)bh * 2048 + bm + lr];
    float* Arow = attn + ((size_t)bh * 2048 + bm + lr) * 2048 + lc * 8;

#define LOAD_STAGE(st, it_) do {                                       \
        cp16(&As[st][lr][lc * 8], Ebase + (size_t)(it_) * 16);         \
        if (tid < 128)                                                 \
            cp16(&Vs[st][vkr][vch * 8], Vbase + (size_t)(it_) * 1024); \
        CP_COMMIT();                                                   \
    } while (0)

    LOAD_STAGE(0, 0);
    LOAD_STAGE(1, 1);
    LOAD_STAGE(2, 2);
    LOAD_STAGE(3, 3);
    LOAD_STAGE(4, 4);

    float acc[2][4][4] = {};

    for (int it = 0; it < 128; ++it) {
        const int st = it % 6;
        if (it + 5 < 128) { CP_WAIT(4); } else { CP_WAIT(0); }
        __syncthreads();
        if (it + 5 < 128) LOAD_STAGE((it + 5) % 6, it + 5);

        // normalized fp32 attn write from smem
        {
            const uint4 ev = *(const uint4*)&As[st][lr][lc * 8];
            const __half2* h2 = (const __half2*)&ev;
            float p[8];
#pragma unroll
            for (int q = 0; q < 4; q++) {
                float2 f = __half22float2(h2[q]);
                p[2 * q]     = f.x * inv;
                p[2 * q + 1] = f.y * inv;
            }
            __stcs((float4*)(Arow + it * 16),     make_float4(p[0], p[1], p[2], p[3]));
            __stcs((float4*)(Arow + it * 16 + 4), make_float4(p[4], p[5], p[6], p[7]));
        }

        uint32_t af[2][4];
#pragma unroll
        for (int mt = 0; mt < 2; mt++)
            ldsm4(af[mt],
                  s2u(&As[st][wm * 32 + mt * 16 + (qd & 1) * 8 + rr][(qd >> 1) * 8]));

        uint32_t bfr[4][2];
#pragma unroll
        for (int np = 0; np < 2; np++) {
            uint32_t bt[4];
            ldsm4t(bt, s2u(&Vs[st][(qd & 1) * 8 + rr]
                                  [wn * 32 + np * 16 + (qd >> 1) * 8]));
            bfr[np * 2][0]     = bt[0];
            bfr[np * 2][1]     = bt[1];
            bfr[np * 2 + 1][0] = bt[2];
            bfr[np * 2 + 1][1] = bt[3];
        }
#pragma unroll
        for (int mt = 0; mt < 2; mt++)
#pragma unroll
            for (int nt = 0; nt < 4; nt++)
                mma_f16(acc[mt][nt], af[mt], bfr[nt]);
    }
#undef LOAD_STAGE

#pragma unroll
    for (int mt = 0; mt < 2; mt++) {
        const int row0 = bm + wm * 32 + mt * 16 + g;
        const float i0 = 1.f / rowsum[(size_t)bh * 2048 + row0];
        const float i1 = 1.f / rowsum[(size_t)bh * 2048 + row0 + 8];
#pragma unroll
        for (int nt = 0; nt < 4; nt++) {
            const int col = wn * 32 + nt * 8 + 2 * t;
            *(float2*)(ctx + ((size_t)b * 2048 + row0) * 1024 + h * 64 + col) =
                make_float2(acc[mt][nt][0] * i0, acc[mt][nt][1] * i0);
            *(float2*)(ctx + ((size_t)b * 2048 + row0 + 8) * 1024 + h * 64 + col) =
                make_float2(acc[mt][nt][2] * i1, acc[mt][nt][3] * i1);
        }
    }
}

// ---------------------------------------------------------------------------
extern "C" void kernel_launch(void* const* d_in, const int* in_sizes, int n_in,
                              void* d_out, int out_size)
{
    const float* q    = (const float*)d_in[0];
    const float* k    = (const float*)d_in[1];
    const float* v    = (const float*)d_in[2];
    const float* mask = (const float*)d_in[3];
    const float* Wq   = (const float*)d_in[4];
    const float* bq   = (const float*)d_in[5];
    const float* Wk   = (const float*)d_in[6];
    const float* bk   = (const float*)d_in[7];
    const float* Wv   = (const float*)d_in[8];
    const float* bv   = (const float*)d_in[9];
    const float* Wo   = (const float*)d_in[10];
    const float* bo   = (const float*)d_in[11];

    float* out  = (float*)d_out;
    float* attn = out + (size_t)BSz * Dd;

    __nv_bfloat16 *Qhi, *Qlo, *Khi, *Klo, *Vhi, *Vlo;
    float *ctxp, *rowsum;
    __half* E;
    cudaGetSymbolAddress((void**)&Qhi, g_Qhi);
    cudaGetSymbolAddress((void**)&Qlo, g_Qlo);
    cudaGetSymbolAddress((void**)&Khi, g_Khi);
    cudaGetSymbolAddress((void**)&Klo, g_Klo);
    cudaGetSymbolAddress((void**)&Vhi, g_Vhi);
    cudaGetSymbolAddress((void**)&Vlo, g_Vlo);
    cudaGetSymbolAddress((void**)&ctxp, g_ctx);
    cudaGetSymbolAddress((void**)&rowsum, g_rowsum);
    cudaGetSymbolAddress((void**)&E, g_e);

    cudaFuncSetAttribute(logits_k, cudaFuncAttributeMaxDynamicSharedMemorySize, 73728);
    cudaFuncSetAttribute(ctx_k, cudaFuncAttributeMaxDynamicSharedMemorySize, CTX_SMEM);

    zero_k<<<512, 256>>>(rowsum, BH * Ss);

    proj_k<0><<<dim3(8, 64, 3), 512>>>(q, k, v, Wq, Wk, Wv, bq, bk, bv,
                                       Qhi, Qlo, Khi, Klo, Vhi, Vlo, nullptr);

    logits_k<<<dim3(16, 16, 64), 512, 73728>>>(Qhi, Qlo, Khi, Klo, mask, E, rowsum);

    ctx_k<<<dim3(16, 1, 64), 256, CTX_SMEM>>>(E, (const __half*)Vhi,
                                              rowsum, attn, ctxp);

    proj_k<1><<<dim3(8, 64, 1), 512>>>(ctxp, ctxp, ctxp, Wo, Wo, Wo, bo, bo, bo,
                                       nullptr, nullptr, nullptr, nullptr,
                                       nullptr, nullptr, out);
}